// round 1
// baseline (speedup 1.0000x reference)
#include <cuda_runtime.h>
#include <cuda_bf16.h>
#include <math.h>

// Problem dims
#define NN      8192
#define IN_DIM  1024
#define H1      512
#define H2      256
#define ZD      192     // Z1+Z2+Z3
#define CAP     192     // max nnz per adj row (mean ~34, sigma ~5.7 -> huge margin)

// ---------------- device scratch (no allocation allowed) ----------------
__device__ float g_t1[NN * H1];     // x @ W1^T
__device__ float g_x1[NN * H1];     // relu(adj @ t1)
__device__ float g_t2[NN * H2];     // x1 @ W2^T
__device__ float g_x2[NN * H2];     // relu(adj @ t2)
__device__ float g_tm[NN * ZD];     // x2 @ [Wm1;Wm2;Wm3]^T
__device__ float g_z [NN * ZD];     // adj @ tm
__device__ float g_tz[NN * ZD];     // leaky(z @ Wt^T + bt)
__device__ float g_vals[NN * CAP];
__device__ int   g_cols[NN * CAP];
__device__ int   g_cnt [NN];

// ---------------- CSR build: one warp per adj row ----------------
__global__ void build_csr_kernel(const float* __restrict__ adj) {
    int row  = blockIdx.x * (blockDim.x >> 5) + (threadIdx.x >> 5);
    int lane = threadIdx.x & 31;
    if (row >= NN) return;
    const float* arow = adj + (size_t)row * NN;
    int cnt = 0;
    for (int c0 = 0; c0 < NN; c0 += 32) {
        float v = arow[c0 + lane];
        unsigned m = __ballot_sync(0xffffffffu, v != 0.0f);
        if (v != 0.0f) {
            int pos = cnt + __popc(m & ((1u << lane) - 1u));
            if (pos < CAP) {
                g_cols[row * CAP + pos] = c0 + lane;
                g_vals[row * CAP + pos] = v;
            }
        }
        cnt += __popc(m);
    }
    if (lane == 0) g_cnt[row] = (cnt < CAP) ? cnt : CAP;
}

// ---------------- SpMM: out_row = sum_j val_j * X[col_j, :] ----------------
// MODE 0: scratch = acc,        out = acc        (z path)
// MODE 1: scratch = relu(acc),  out = sigmoid(relu(acc))   (x1/x2 path)
template <int MODE>
__global__ void __launch_bounds__(256) spmm_kernel(
    const float* __restrict__ X, int ncols,
    float* __restrict__ scratch, float* __restrict__ out)
{
    int row = blockIdx.x;
    int col = blockIdx.y * 256 + threadIdx.x;
    if (col >= ncols) return;
    int cnt = g_cnt[row];
    const int*   cols = g_cols + row * CAP;
    const float* vals = g_vals + row * CAP;

    float a0 = 0.f, a1 = 0.f, a2 = 0.f, a3 = 0.f;
    int j = 0;
    for (; j + 4 <= cnt; j += 4) {
        int   c0 = cols[j+0], c1 = cols[j+1], c2 = cols[j+2], c3 = cols[j+3];
        float v0 = vals[j+0], v1 = vals[j+1], v2 = vals[j+2], v3 = vals[j+3];
        a0 += v0 * X[(size_t)c0 * ncols + col];
        a1 += v1 * X[(size_t)c1 * ncols + col];
        a2 += v2 * X[(size_t)c2 * ncols + col];
        a3 += v3 * X[(size_t)c3 * ncols + col];
    }
    for (; j < cnt; j++)
        a0 += vals[j] * X[(size_t)cols[j] * ncols + col];
    float acc = (a0 + a1) + (a2 + a3);

    size_t o = (size_t)row * ncols + col;
    if (MODE == 1) {
        float r = acc > 0.f ? acc : 0.f;
        scratch[o] = r;
        out[o]     = 1.0f / (1.0f + __expf(-r));
    } else {
        scratch[o] = acc;
        out[o]     = acc;
    }
}

// ---------------- NT SGEMM: C[M,N] = A[M,K] * B[N,K]^T (+ epilogue) ----------------
// EPI 0: plain store. EPI 1: c += bias[n]; leaky_relu(c, 0.1)
// Requirements: M % 128 == 0, K % 16 == 0, lda/ldb multiples of 4, 16B-aligned rows.
#define BM 128
#define BN 128
#define BK 16

template <int EPI>
__global__ void __launch_bounds__(256) gemm_nt_kernel(
    const float* __restrict__ A, const float* __restrict__ B,
    const float* __restrict__ bias, float* __restrict__ C,
    int M, int N, int K, int lda, int ldb, int ldc)
{
    __shared__ float As[BK][BM];
    __shared__ float Bs[BK][BN];

    int tid = threadIdx.x;
    int m0 = blockIdx.y * BM;
    int n0 = blockIdx.x * BN;
    int tx = tid & 15;          // 16 cols of threads -> n
    int ty = tid >> 4;          // 16 rows of threads -> m

    float acc[8][8];
    #pragma unroll
    for (int i = 0; i < 8; i++)
        #pragma unroll
        for (int jj = 0; jj < 8; jj++) acc[i][jj] = 0.f;

    for (int k0 = 0; k0 < K; k0 += BK) {
        // A tile: 128 rows x 16 k = 512 float4, 2 per thread
        #pragma unroll
        for (int i = 0; i < 2; i++) {
            int f = tid + i * 256;
            int r = f >> 2;
            int kq = (f & 3) * 4;
            float4 v = *(const float4*)(A + (size_t)(m0 + r) * lda + k0 + kq);
            As[kq + 0][r] = v.x; As[kq + 1][r] = v.y;
            As[kq + 2][r] = v.z; As[kq + 3][r] = v.w;
        }
        // B tile (row-guarded: N may be < n0+r+1)
        #pragma unroll
        for (int i = 0; i < 2; i++) {
            int f = tid + i * 256;
            int r = f >> 2;
            int kq = (f & 3) * 4;
            float4 v = make_float4(0.f, 0.f, 0.f, 0.f);
            if (n0 + r < N)
                v = *(const float4*)(B + (size_t)(n0 + r) * ldb + k0 + kq);
            Bs[kq + 0][r] = v.x; Bs[kq + 1][r] = v.y;
            Bs[kq + 2][r] = v.z; Bs[kq + 3][r] = v.w;
        }
        __syncthreads();

        #pragma unroll
        for (int k = 0; k < BK; k++) {
            float a[8], b[8];
            float4 av0 = *(const float4*)&As[k][ty * 8];
            float4 av1 = *(const float4*)&As[k][ty * 8 + 4];
            float4 bv0 = *(const float4*)&Bs[k][tx * 8];
            float4 bv1 = *(const float4*)&Bs[k][tx * 8 + 4];
            a[0]=av0.x; a[1]=av0.y; a[2]=av0.z; a[3]=av0.w;
            a[4]=av1.x; a[5]=av1.y; a[6]=av1.z; a[7]=av1.w;
            b[0]=bv0.x; b[1]=bv0.y; b[2]=bv0.z; b[3]=bv0.w;
            b[4]=bv1.x; b[5]=bv1.y; b[6]=bv1.z; b[7]=bv1.w;
            #pragma unroll
            for (int i = 0; i < 8; i++)
                #pragma unroll
                for (int jj = 0; jj < 8; jj++)
                    acc[i][jj] += a[i] * b[jj];
        }
        __syncthreads();
    }

    #pragma unroll
    for (int i = 0; i < 8; i++) {
        int m = m0 + ty * 8 + i;
        #pragma unroll
        for (int jj = 0; jj < 8; jj++) {
            int n = n0 + tx * 8 + jj;
            if (n < N) {
                float c = acc[i][jj];
                if (EPI == 1) {
                    c += bias[n];
                    c = (c >= 0.f) ? c : 0.1f * c;
                }
                C[(size_t)m * ldc + n] = c;
            }
        }
    }
}

// ---------------- launch ----------------
static inline void* sym_addr(const void* sym) {
    void* p = nullptr;
    cudaGetSymbolAddress(&p, sym);
    return p;
}

extern "C" void kernel_launch(void* const* d_in, const int* in_sizes, int n_in,
                              void* d_out, int out_size)
{
    const float* adj = (const float*)d_in[0];
    const float* x   = (const float*)d_in[1];
    const float* W1  = (const float*)d_in[2];
    const float* W2  = (const float*)d_in[3];
    const float* Wm1 = (const float*)d_in[4];
    const float* Wm2 = (const float*)d_in[5];
    const float* Wm3 = (const float*)d_in[6];
    const float* Wt  = (const float*)d_in[7];
    const float* bt  = (const float*)d_in[8];

    float* out = (float*)d_out;
    float* out_pred = out;                                   // [8192, 8192]
    float* out_x1   = out + (size_t)NN * NN;                 // sigmoid(x1) [8192, 512]
    float* out_x2   = out_x1 + (size_t)NN * H1;              // sigmoid(x2) [8192, 256]
    float* out_z    = out_x2 + (size_t)NN * H2;              // z [8192, 192]

    float* t1 = (float*)sym_addr(g_t1);
    float* x1 = (float*)sym_addr(g_x1);
    float* t2 = (float*)sym_addr(g_t2);
    float* x2 = (float*)sym_addr(g_x2);
    float* tm = (float*)sym_addr(g_tm);
    float* z  = (float*)sym_addr(g_z);
    float* tz = (float*)sym_addr(g_tz);

    // 1. sparsify adj -> CSR (deterministic, rebuilt every call)
    build_csr_kernel<<<NN / 8, 256>>>(adj);

    // 2. t1 = x @ W1^T        [8192,1024] x [512,1024]^T -> [8192,512]
    {
        dim3 grid((H1 + BN - 1) / BN, NN / BM);
        gemm_nt_kernel<0><<<grid, 256>>>(x, W1, nullptr, t1,
                                         NN, H1, IN_DIM, IN_DIM, IN_DIM, H1);
    }
    // 3. x1 = relu(adj @ t1);  out_x1 = sigmoid(x1)
    {
        dim3 grid(NN, (H1 + 255) / 256);
        spmm_kernel<1><<<grid, 256>>>(t1, H1, x1, out_x1);
    }
    // 4. t2 = x1 @ W2^T
    {
        dim3 grid((H2 + BN - 1) / BN, NN / BM);
        gemm_nt_kernel<0><<<grid, 256>>>(x1, W2, nullptr, t2,
                                         NN, H2, H1, H1, H1, H2);
    }
    // 5. x2 = relu(adj @ t2);  out_x2 = sigmoid(x2)
    {
        dim3 grid(NN, (H2 + 255) / 256);
        spmm_kernel<1><<<grid, 256>>>(t2, H2, x2, out_x2);
    }
    // 6. tm = x2 @ [Wm1;Wm2;Wm3]^T  (three N=64 GEMMs into strided columns of tm)
    {
        dim3 grid(1, NN / BM);
        gemm_nt_kernel<0><<<grid, 256>>>(x2, Wm1, nullptr, tm,       NN, 64, H2, H2, H2, ZD);
        gemm_nt_kernel<0><<<grid, 256>>>(x2, Wm2, nullptr, tm + 64,  NN, 64, H2, H2, H2, ZD);
        gemm_nt_kernel<0><<<grid, 256>>>(x2, Wm3, nullptr, tm + 128, NN, 64, H2, H2, H2, ZD);
    }
    // 7. z = adj @ tm;  out_z = z
    {
        dim3 grid(NN, 1);
        spmm_kernel<0><<<grid, 256>>>(tm, ZD, z, out_z);
    }
    // 8. tz = leaky_relu(z @ Wt^T + bt, 0.1)
    {
        dim3 grid((ZD + BN - 1) / BN, NN / BM);
        gemm_nt_kernel<1><<<grid, 256>>>(z, Wt, bt, tz,
                                         NN, ZD, ZD, ZD, ZD, ZD);
    }
    // 9. pred = z @ tz^T   [8192,192] x [8192,192]^T -> [8192,8192]
    {
        dim3 grid(NN / BN, NN / BM);
        gemm_nt_kernel<0><<<grid, 256>>>(z, tz, nullptr, out_pred,
                                         NN, NN, ZD, ZD, ZD, NN);
    }
    (void)in_sizes; (void)n_in; (void)out_size;
}

// round 3
// speedup vs baseline: 2.0034x; 2.0034x over previous
#include <cuda_runtime.h>
#include <cuda_bf16.h>
#include <math.h>
#include <stdint.h>

// Problem dims
#define NN      8192
#define IN_DIM  1024
#define H1      512
#define H2      256
#define ZD      192     // Z1+Z2+Z3
#define CAP     192     // max nnz per adj row (mean ~34 -> huge margin)

// ---------------- device scratch (no allocation allowed) ----------------
__device__ float g_t1[NN * H1];
__device__ float g_x1[NN * H1];
__device__ float g_t2[NN * H2];
__device__ float g_x2[NN * H2];
__device__ float g_tm[NN * ZD];
__device__ float g_z [NN * ZD];
__device__ float g_tz[NN * ZD];
__device__ float g_vals[NN * CAP];
__device__ int   g_cols[NN * CAP];
__device__ int   g_cnt [NN];

// ---------------- CSR build: one warp per adj row ----------------
__global__ void build_csr_kernel(const float* __restrict__ adj) {
    int row  = blockIdx.x * (blockDim.x >> 5) + (threadIdx.x >> 5);
    int lane = threadIdx.x & 31;
    if (row >= NN) return;
    const float* arow = adj + (size_t)row * NN;
    int cnt = 0;
    for (int c0 = 0; c0 < NN; c0 += 32) {
        float v = arow[c0 + lane];
        unsigned m = __ballot_sync(0xffffffffu, v != 0.0f);
        if (v != 0.0f) {
            int pos = cnt + __popc(m & ((1u << lane) - 1u));
            if (pos < CAP) {
                g_cols[row * CAP + pos] = c0 + lane;
                g_vals[row * CAP + pos] = v;
            }
        }
        cnt += __popc(m);
    }
    if (lane == 0) g_cnt[row] = (cnt < CAP) ? cnt : CAP;
}

// ---------------- SpMM ----------------
// MODE 0: scratch = acc, out = acc   MODE 1: scratch = relu, out = sigmoid(relu)
template <int MODE>
__global__ void __launch_bounds__(256) spmm_kernel(
    const float* __restrict__ X, int ncols,
    float* __restrict__ scratch, float* __restrict__ out)
{
    int row = blockIdx.x;
    int col = blockIdx.y * 256 + threadIdx.x;
    if (col >= ncols) return;
    int cnt = g_cnt[row];
    const int*   cols = g_cols + row * CAP;
    const float* vals = g_vals + row * CAP;

    float a0 = 0.f, a1 = 0.f, a2 = 0.f, a3 = 0.f;
    int j = 0;
    for (; j + 4 <= cnt; j += 4) {
        int   c0 = cols[j+0], c1 = cols[j+1], c2 = cols[j+2], c3 = cols[j+3];
        float v0 = vals[j+0], v1 = vals[j+1], v2 = vals[j+2], v3 = vals[j+3];
        a0 += v0 * X[(size_t)c0 * ncols + col];
        a1 += v1 * X[(size_t)c1 * ncols + col];
        a2 += v2 * X[(size_t)c2 * ncols + col];
        a3 += v3 * X[(size_t)c3 * ncols + col];
    }
    for (; j < cnt; j++)
        a0 += vals[j] * X[(size_t)cols[j] * ncols + col];
    float acc = (a0 + a1) + (a2 + a3);

    size_t o = (size_t)row * ncols + col;
    if (MODE == 1) {
        float r = acc > 0.f ? acc : 0.f;
        scratch[o] = r;
        out[o]     = 1.0f / (1.0f + __expf(-r));
    } else {
        scratch[o] = acc;
        out[o]     = acc;
    }
}

// ---------------- bf16x3 split-precision tensor-core NT GEMM ----------------
// C[M,N] = A[M,K] * B[N,K]^T (both K-major), fp32 accumulate.
// Each fp32 value v = hi + lo (bf16 each); product uses hh + hl + lh terms.
// Requirements: M % 128 == 0, K % 32 == 0, lda/ldb % 4 == 0.
// EPI 0: plain store. EPI 1: c += bias[n]; leaky_relu(c, 0.1)

__device__ __forceinline__ void ldsm4(uint32_t& r0, uint32_t& r1, uint32_t& r2,
                                      uint32_t& r3, uint32_t addr) {
    asm volatile("ldmatrix.sync.aligned.m8n8.x4.shared.b16 {%0,%1,%2,%3}, [%4];"
                 : "=r"(r0), "=r"(r1), "=r"(r2), "=r"(r3) : "r"(addr));
}

__device__ __forceinline__ void mma_bf16(float (&d)[4], const uint32_t (&a)[4],
                                         uint32_t b0, uint32_t b1) {
    asm volatile(
        "mma.sync.aligned.m16n8k16.row.col.f32.bf16.bf16.f32 "
        "{%0,%1,%2,%3}, {%4,%5,%6,%7}, {%8,%9}, {%0,%1,%2,%3};"
        : "+f"(d[0]), "+f"(d[1]), "+f"(d[2]), "+f"(d[3])
        : "r"(a[0]), "r"(a[1]), "r"(a[2]), "r"(a[3]), "r"(b0), "r"(b1));
}

// pack 2 fp32 -> (hi bf16x2, lo bf16x2)
__device__ __forceinline__ void split2(float v0, float v1, uint32_t& hi, uint32_t& lo) {
    __nv_bfloat16 h0 = __float2bfloat16_rn(v0);
    __nv_bfloat16 h1 = __float2bfloat16_rn(v1);
    __nv_bfloat16 l0 = __float2bfloat16_rn(v0 - __bfloat162float(h0));
    __nv_bfloat16 l1 = __float2bfloat16_rn(v1 - __bfloat162float(h1));
    hi = (uint32_t)__bfloat16_as_ushort(h0) | ((uint32_t)__bfloat16_as_ushort(h1) << 16);
    lo = (uint32_t)__bfloat16_as_ushort(l0) | ((uint32_t)__bfloat16_as_ushort(l1) << 16);
}

#define GBM 128
#define GBN 128
#define GBK 32   // K per tile (bf16 elems); row = 64 bytes = 4 x 16B chunks

// swizzled byte offset for (row, kchunk) in a 128x32 bf16 tile (64B rows)
__device__ __forceinline__ uint32_t sw_off(int r, int kc) {
    return (uint32_t)(r * 64 + ((kc ^ ((r >> 1) & 3)) << 4));
}

template <int EPI>
__global__ void __launch_bounds__(256) gemm_bf16x3_nt(
    const float* __restrict__ A, const float* __restrict__ B,
    const float* __restrict__ bias, float* __restrict__ C,
    int M, int N, int K, int lda, int ldb, int ldc)
{
    __shared__ __align__(128) uint8_t AsHi[GBM * 64];
    __shared__ __align__(128) uint8_t AsLo[GBM * 64];
    __shared__ __align__(128) uint8_t BsHi[GBN * 64];
    __shared__ __align__(128) uint8_t BsLo[GBN * 64];

    const int tid  = threadIdx.x;
    const int lane = tid & 31;
    const int wid  = tid >> 5;
    const int wm   = wid & 1;            // 2 warps in M -> 64 rows each
    const int wn   = wid >> 1;           // 4 warps in N -> 32 cols each
    const int m0   = blockIdx.y * GBM;
    const int n0   = blockIdx.x * GBN;

    const uint32_t AhB = (uint32_t)__cvta_generic_to_shared(AsHi);
    const uint32_t AlB = (uint32_t)__cvta_generic_to_shared(AsLo);
    const uint32_t BhB = (uint32_t)__cvta_generic_to_shared(BsHi);
    const uint32_t BlB = (uint32_t)__cvta_generic_to_shared(BsLo);

    float acc[4][4][4];
    #pragma unroll
    for (int i = 0; i < 4; i++)
        #pragma unroll
        for (int j = 0; j < 4; j++)
            #pragma unroll
            for (int q = 0; q < 4; q++) acc[i][j][q] = 0.f;

    float4 pa[4], pb[4];

    // prefetch tile 0: A tile 128 rows x 8 quads, 1024 quads / 256 thr = 4 each
    #pragma unroll
    for (int i = 0; i < 4; i++) {
        int f = tid + i * 256;
        int r = f >> 3, q = f & 7;
        pa[i] = *(const float4*)(A + (size_t)(m0 + r) * lda + q * 4);
        if (n0 + r < N)
            pb[i] = *(const float4*)(B + (size_t)(n0 + r) * ldb + q * 4);
        else
            pb[i] = make_float4(0.f, 0.f, 0.f, 0.f);
    }

    const int nIt = K >> 5;
    for (int it = 0; it < nIt; it++) {
        __syncthreads();
        // split fp32 -> bf16 hi/lo and store swizzled
        #pragma unroll
        for (int i = 0; i < 4; i++) {
            int f = tid + i * 256;
            int r = f >> 3, q = f & 7;
            uint32_t off = sw_off(r, q >> 1) + (q & 1) * 8;
            uint2 h, l;
            split2(pa[i].x, pa[i].y, h.x, l.x);
            split2(pa[i].z, pa[i].w, h.y, l.y);
            *(uint2*)(AsHi + off) = h;
            *(uint2*)(AsLo + off) = l;
            split2(pb[i].x, pb[i].y, h.x, l.x);
            split2(pb[i].z, pb[i].w, h.y, l.y);
            *(uint2*)(BsHi + off) = h;
            *(uint2*)(BsLo + off) = l;
        }
        __syncthreads();

        // prefetch next tile (overlaps with mma below)
        if (it + 1 < nIt) {
            int k0 = (it + 1) << 5;
            #pragma unroll
            for (int i = 0; i < 4; i++) {
                int f = tid + i * 256;
                int r = f >> 3, q = f & 7;
                pa[i] = *(const float4*)(A + (size_t)(m0 + r) * lda + k0 + q * 4);
                if (n0 + r < N)
                    pb[i] = *(const float4*)(B + (size_t)(n0 + r) * ldb + k0 + q * 4);
                else
                    pb[i] = make_float4(0.f, 0.f, 0.f, 0.f);
            }
        }

        // 2 k16-steps per tile
        #pragma unroll
        for (int ks = 0; ks < 2; ks++) {
            uint32_t a[4][4], bh[2][4], bl[2][4];
            // B hi/lo fragments: 16 n-rows x 2 k8-chunks each half
            #pragma unroll
            for (int nh = 0; nh < 2; nh++) {
                int rr = wn * 32 + nh * 16 + (lane >> 4) * 8 + (lane & 7);
                int kc = ks * 2 + ((lane >> 3) & 1);
                uint32_t off = sw_off(rr, kc);
                ldsm4(bh[nh][0], bh[nh][1], bh[nh][2], bh[nh][3], BhB + off);
                ldsm4(bl[nh][0], bl[nh][1], bl[nh][2], bl[nh][3], BlB + off);
            }
            // A hi fragments
            #pragma unroll
            for (int mt = 0; mt < 4; mt++) {
                int rr = wm * 64 + mt * 16 + ((lane >> 3) & 1) * 8 + (lane & 7);
                int kc = ks * 2 + (lane >> 4);
                ldsm4(a[mt][0], a[mt][1], a[mt][2], a[mt][3], AhB + sw_off(rr, kc));
            }
            // hh + hl
            #pragma unroll
            for (int mt = 0; mt < 4; mt++)
                #pragma unroll
                for (int nt = 0; nt < 4; nt++)
                    mma_bf16(acc[mt][nt], a[mt],
                             bh[nt >> 1][(nt & 1) * 2], bh[nt >> 1][(nt & 1) * 2 + 1]);
            #pragma unroll
            for (int mt = 0; mt < 4; mt++)
                #pragma unroll
                for (int nt = 0; nt < 4; nt++)
                    mma_bf16(acc[mt][nt], a[mt],
                             bl[nt >> 1][(nt & 1) * 2], bl[nt >> 1][(nt & 1) * 2 + 1]);
            // A lo fragments (reuse regs)
            #pragma unroll
            for (int mt = 0; mt < 4; mt++) {
                int rr = wm * 64 + mt * 16 + ((lane >> 3) & 1) * 8 + (lane & 7);
                int kc = ks * 2 + (lane >> 4);
                ldsm4(a[mt][0], a[mt][1], a[mt][2], a[mt][3], AlB + sw_off(rr, kc));
            }
            // lh
            #pragma unroll
            for (int mt = 0; mt < 4; mt++)
                #pragma unroll
                for (int nt = 0; nt < 4; nt++)
                    mma_bf16(acc[mt][nt], a[mt],
                             bh[nt >> 1][(nt & 1) * 2], bh[nt >> 1][(nt & 1) * 2 + 1]);
        }
    }

    // epilogue: c0,c1 at (row, col..col+1), c2,c3 at (row+8, ...)
    #pragma unroll
    for (int mt = 0; mt < 4; mt++) {
        int row = m0 + wm * 64 + mt * 16 + (lane >> 2);
        #pragma unroll
        for (int nt = 0; nt < 4; nt++) {
            int col = n0 + wn * 32 + nt * 8 + (lane & 3) * 2;
            if (col < N) {
                float c0 = acc[mt][nt][0], c1 = acc[mt][nt][1];
                float c2 = acc[mt][nt][2], c3 = acc[mt][nt][3];
                if (EPI == 1) {
                    float b0 = bias[col], b1 = bias[col + 1];
                    c0 += b0; c1 += b1; c2 += b0; c3 += b1;
                    c0 = (c0 >= 0.f) ? c0 : 0.1f * c0;
                    c1 = (c1 >= 0.f) ? c1 : 0.1f * c1;
                    c2 = (c2 >= 0.f) ? c2 : 0.1f * c2;
                    c3 = (c3 >= 0.f) ? c3 : 0.1f * c3;
                }
                *(float2*)(C + (size_t)row * ldc + col)       = make_float2(c0, c1);
                *(float2*)(C + (size_t)(row + 8) * ldc + col) = make_float2(c2, c3);
            }
        }
    }
}

// ---------------- launch ----------------
static inline void* sym_addr(const void* sym) {
    void* p = nullptr;
    cudaGetSymbolAddress(&p, sym);
    return p;
}

extern "C" void kernel_launch(void* const* d_in, const int* in_sizes, int n_in,
                              void* d_out, int out_size)
{
    const float* adj = (const float*)d_in[0];
    const float* x   = (const float*)d_in[1];
    const float* W1  = (const float*)d_in[2];
    const float* W2  = (const float*)d_in[3];
    const float* Wm1 = (const float*)d_in[4];
    const float* Wm2 = (const float*)d_in[5];
    const float* Wm3 = (const float*)d_in[6];
    const float* Wt  = (const float*)d_in[7];
    const float* bt  = (const float*)d_in[8];

    float* out = (float*)d_out;
    float* out_pred = out;
    float* out_x1   = out + (size_t)NN * NN;
    float* out_x2   = out_x1 + (size_t)NN * H1;
    float* out_z    = out_x2 + (size_t)NN * H2;

    float* t1 = (float*)sym_addr(g_t1);
    float* x1 = (float*)sym_addr(g_x1);
    float* t2 = (float*)sym_addr(g_t2);
    float* x2 = (float*)sym_addr(g_x2);
    float* tm = (float*)sym_addr(g_tm);
    float* z  = (float*)sym_addr(g_z);
    float* tz = (float*)sym_addr(g_tz);

    // 1. sparsify adj -> CSR
    build_csr_kernel<<<NN / 8, 256>>>(adj);

    // 2. t1 = x @ W1^T
    {
        dim3 grid(H1 / GBN, NN / GBM);
        gemm_bf16x3_nt<0><<<grid, 256>>>(x, W1, nullptr, t1,
                                         NN, H1, IN_DIM, IN_DIM, IN_DIM, H1);
    }
    // 3. x1 = relu(adj @ t1); out_x1 = sigmoid(x1)
    {
        dim3 grid(NN, (H1 + 255) / 256);
        spmm_kernel<1><<<grid, 256>>>(t1, H1, x1, out_x1);
    }
    // 4. t2 = x1 @ W2^T
    {
        dim3 grid(H2 / GBN, NN / GBM);
        gemm_bf16x3_nt<0><<<grid, 256>>>(x1, W2, nullptr, t2,
                                         NN, H2, H1, H1, H1, H2);
    }
    // 5. x2 = relu(adj @ t2); out_x2 = sigmoid(x2)
    {
        dim3 grid(NN, (H2 + 255) / 256);
        spmm_kernel<1><<<grid, 256>>>(t2, H2, x2, out_x2);
    }
    // 6. tm = x2 @ [Wm1;Wm2;Wm3]^T  (three N=64 GEMMs, strided columns)
    {
        dim3 grid(1, NN / GBM);
        gemm_bf16x3_nt<0><<<grid, 256>>>(x2, Wm1, nullptr, tm,       NN, 64, H2, H2, H2, ZD);
        gemm_bf16x3_nt<0><<<grid, 256>>>(x2, Wm2, nullptr, tm + 64,  NN, 64, H2, H2, H2, ZD);
        gemm_bf16x3_nt<0><<<grid, 256>>>(x2, Wm3, nullptr, tm + 128, NN, 64, H2, H2, H2, ZD);
    }
    // 7. z = adj @ tm; out_z = z
    {
        dim3 grid(NN, 1);
        spmm_kernel<0><<<grid, 256>>>(tm, ZD, z, out_z);
    }
    // 8. tz = leaky_relu(z @ Wt^T + bt, 0.1)
    {
        dim3 grid((ZD + GBN - 1) / GBN, NN / GBM);
        gemm_bf16x3_nt<1><<<grid, 256>>>(z, Wt, bt, tz,
                                         NN, ZD, ZD, ZD, ZD, ZD);
    }
    // 9. pred = z @ tz^T
    {
        dim3 grid(NN / GBN, NN / GBM);
        gemm_bf16x3_nt<0><<<grid, 256>>>(z, tz, nullptr, out_pred,
                                         NN, NN, ZD, ZD, ZD, NN);
    }
    (void)in_sizes; (void)n_in; (void)out_size;
}

// round 4
// speedup vs baseline: 2.5748x; 1.2852x over previous
#include <cuda_runtime.h>
#include <cuda_bf16.h>
#include <math.h>
#include <stdint.h>

// Problem dims
#define NN      8192
#define IN_DIM  1024
#define H1      512
#define H2      256
#define ZD      192
#define CAP     192

// ---------------- device scratch ----------------
__device__ float g_t1[NN * H1];
__device__ float g_t2[NN * H2];
__device__ float g_tm[NN * ZD];
__device__ __nv_bfloat16 g_xh [NN * IN_DIM];
__device__ __nv_bfloat16 g_xl [NN * IN_DIM];
__device__ __nv_bfloat16 g_x1h[NN * H1];
__device__ __nv_bfloat16 g_x1l[NN * H1];
__device__ __nv_bfloat16 g_x2h[NN * H2];
__device__ __nv_bfloat16 g_x2l[NN * H2];
__device__ __nv_bfloat16 g_zh [NN * ZD];
__device__ __nv_bfloat16 g_zl [NN * ZD];
__device__ __nv_bfloat16 g_tzh[NN * ZD];
__device__ __nv_bfloat16 g_tzl[NN * ZD];
__device__ __nv_bfloat16 g_W1h[H1 * IN_DIM];
__device__ __nv_bfloat16 g_W1l[H1 * IN_DIM];
__device__ __nv_bfloat16 g_W2h[H2 * H1];
__device__ __nv_bfloat16 g_W2l[H2 * H1];
__device__ __nv_bfloat16 g_Wmh[ZD * H2];
__device__ __nv_bfloat16 g_Wml[ZD * H2];
__device__ __nv_bfloat16 g_Wth[ZD * ZD];
__device__ __nv_bfloat16 g_Wtl[ZD * ZD];
__device__ float g_vals[NN * CAP];
__device__ int   g_cols[NN * CAP];
__device__ int   g_cnt [NN];

// ---------------- helpers ----------------
__device__ __forceinline__ void split2(float v0, float v1, uint32_t& hi, uint32_t& lo) {
    __nv_bfloat16 h0 = __float2bfloat16_rn(v0);
    __nv_bfloat16 h1 = __float2bfloat16_rn(v1);
    __nv_bfloat16 l0 = __float2bfloat16_rn(v0 - __bfloat162float(h0));
    __nv_bfloat16 l1 = __float2bfloat16_rn(v1 - __bfloat162float(h1));
    hi = (uint32_t)__bfloat16_as_ushort(h0) | ((uint32_t)__bfloat16_as_ushort(h1) << 16);
    lo = (uint32_t)__bfloat16_as_ushort(l0) | ((uint32_t)__bfloat16_as_ushort(l1) << 16);
}

__device__ __forceinline__ void ldsm4(uint32_t& r0, uint32_t& r1, uint32_t& r2,
                                      uint32_t& r3, uint32_t addr) {
    asm volatile("ldmatrix.sync.aligned.m8n8.x4.shared.b16 {%0,%1,%2,%3}, [%4];"
                 : "=r"(r0), "=r"(r1), "=r"(r2), "=r"(r3) : "r"(addr));
}

__device__ __forceinline__ void mma_bf16(float (&d)[4], const uint32_t (&a)[4],
                                         uint32_t b0, uint32_t b1) {
    asm volatile(
        "mma.sync.aligned.m16n8k16.row.col.f32.bf16.bf16.f32 "
        "{%0,%1,%2,%3}, {%4,%5,%6,%7}, {%8,%9}, {%0,%1,%2,%3};"
        : "+f"(d[0]), "+f"(d[1]), "+f"(d[2]), "+f"(d[3])
        : "r"(a[0]), "r"(a[1]), "r"(a[2]), "r"(a[3]), "r"(b0), "r"(b1));
}

__device__ __forceinline__ void cp16(uint32_t dst, const void* src, bool v) {
    int sz = v ? 16 : 0;
    asm volatile("cp.async.cg.shared.global [%0], [%1], 16, %2;\n"
                 :: "r"(dst), "l"(src), "r"(sz) : "memory");
}
__device__ __forceinline__ void cp_commit() {
    asm volatile("cp.async.commit_group;" ::: "memory");
}
template <int n>
__device__ __forceinline__ void cp_wait() {
    asm volatile("cp.async.wait_group %0;" :: "n"(n) : "memory");
}

// ---------------- split fp32 -> bf16 hi/lo planes ----------------
__global__ void split_kernel(const float4* __restrict__ src,
                             uint32_t* __restrict__ hi, uint32_t* __restrict__ lo,
                             int nq) {
    int i = blockIdx.x * 256 + threadIdx.x;
    if (i >= nq) return;
    float4 v = src[i];
    uint32_t h0, l0, h1, l1;
    split2(v.x, v.y, h0, l0);
    split2(v.z, v.w, h1, l1);
    hi[i * 2]     = h0; hi[i * 2 + 1] = h1;
    lo[i * 2]     = l0; lo[i * 2 + 1] = l1;
}

// ---------------- CSR build: one warp per adj row, float4 + warp scan ----------------
__global__ void build_csr_kernel(const float* __restrict__ adj) {
    int row  = blockIdx.x * (blockDim.x >> 5) + (threadIdx.x >> 5);
    int lane = threadIdx.x & 31;
    if (row >= NN) return;
    const float* arow = adj + (size_t)row * NN;
    int cnt = 0;
    for (int c0 = 0; c0 < NN; c0 += 128) {
        float4 v = *(const float4*)(arow + c0 + lane * 4);
        unsigned m = (v.x != 0.f ? 1u : 0u) | (v.y != 0.f ? 2u : 0u)
                   | (v.z != 0.f ? 4u : 0u) | (v.w != 0.f ? 8u : 0u);
        int c = __popc(m);
        int s = c;
        #pragma unroll
        for (int d = 1; d < 32; d <<= 1) {
            int t = __shfl_up_sync(0xffffffffu, s, d);
            if (lane >= d) s += t;
        }
        int pos = cnt + s - c;           // exclusive prefix
        int base = c0 + lane * 4;
        float vv[4] = {v.x, v.y, v.z, v.w};
        #pragma unroll
        for (int e = 0; e < 4; e++) {
            if ((m >> e) & 1u) {
                if (pos < CAP) {
                    g_cols[row * CAP + pos] = base + e;
                    g_vals[row * CAP + pos] = vv[e];
                }
                pos++;
            }
        }
        cnt += __shfl_sync(0xffffffffu, s, 31);
    }
    if (lane == 0) g_cnt[row] = (cnt < CAP) ? cnt : CAP;
}

// ---------------- SpMM ----------------
// MODE 0: out_f32 = acc (z),           planes = split(acc)
// MODE 1: out_f32 = sigmoid(relu(acc)), planes = split(relu(acc))
template <int MODE>
__global__ void __launch_bounds__(256) spmm_kernel(
    const float* __restrict__ X, int ncols,
    float* __restrict__ out_f32,
    __nv_bfloat16* __restrict__ hi, __nv_bfloat16* __restrict__ lo)
{
    int row = blockIdx.x;
    int col = blockIdx.y * 256 + threadIdx.x;
    if (col >= ncols) return;
    int cnt = g_cnt[row];
    const int*   cols = g_cols + row * CAP;
    const float* vals = g_vals + row * CAP;

    float a0 = 0.f, a1 = 0.f, a2 = 0.f, a3 = 0.f;
    int j = 0;
    for (; j + 4 <= cnt; j += 4) {
        int   c0 = cols[j+0], c1 = cols[j+1], c2 = cols[j+2], c3 = cols[j+3];
        float v0 = vals[j+0], v1 = vals[j+1], v2 = vals[j+2], v3 = vals[j+3];
        a0 += v0 * X[(size_t)c0 * ncols + col];
        a1 += v1 * X[(size_t)c1 * ncols + col];
        a2 += v2 * X[(size_t)c2 * ncols + col];
        a3 += v3 * X[(size_t)c3 * ncols + col];
    }
    for (; j < cnt; j++)
        a0 += vals[j] * X[(size_t)cols[j] * ncols + col];
    float acc = (a0 + a1) + (a2 + a3);

    size_t o = (size_t)row * ncols + col;
    float r = (MODE == 1) ? (acc > 0.f ? acc : 0.f) : acc;
    __nv_bfloat16 h = __float2bfloat16_rn(r);
    hi[o] = h;
    lo[o] = __float2bfloat16_rn(r - __bfloat162float(h));
    out_f32[o] = (MODE == 1) ? (1.0f / (1.0f + __expf(-r))) : acc;
}

// ---------------- bf16x3 GEMM, pre-split planes, cp.async double-buffered ----
// C[M,N] = A[M,K] * B[N,K]^T ; A,B given as bf16 hi/lo planes (ld = K).
// EPI 0: fp32 store to C.  EPI 1: +bias, leaky_relu(0.1), split -> Ch/Cl planes.
#define GBM 128
#define GBN 128
#define GBK 64
#define STG_BYTES 65536           // 4 planes * 16KB
#define SMEM_BYTES (2 * STG_BYTES)
#define PL_AH 0
#define PL_AL 16384
#define PL_BH 32768
#define PL_BL 49152

template <int EPI>
__global__ void __launch_bounds__(256, 1) gemm3(
    const __nv_bfloat16* __restrict__ Ah, const __nv_bfloat16* __restrict__ Al,
    const __nv_bfloat16* __restrict__ Bh, const __nv_bfloat16* __restrict__ Bl,
    const float* __restrict__ bias, float* __restrict__ C,
    __nv_bfloat16* __restrict__ Ch, __nv_bfloat16* __restrict__ Cl,
    int M, int N, int K, int ldc)
{
    extern __shared__ uint8_t smem[];
    const uint32_t sbase = (uint32_t)__cvta_generic_to_shared(smem);

    const int tid  = threadIdx.x;
    const int lane = tid & 31;
    const int wid  = tid >> 5;
    const int wm   = wid & 1;
    const int wn   = wid >> 1;
    const int m0   = blockIdx.y * GBM;
    const int n0   = blockIdx.x * GBN;

    float acc[4][4][4];
    #pragma unroll
    for (int i = 0; i < 4; i++)
        #pragma unroll
        for (int j = 0; j < 4; j++)
            #pragma unroll
            for (int q = 0; q < 4; q++) acc[i][j][q] = 0.f;

    // tile loader: 1024 16B-chunks per plane, 4 per thread per plane
    auto load_tile = [&](int it, int s) {
        int k0 = it * GBK;
        uint32_t st = sbase + s * STG_BYTES;
        #pragma unroll
        for (int i = 0; i < 4; i++) {
            int f = tid + i * 256;
            int r = f >> 3, c = f & 7;
            uint32_t doff = (uint32_t)(r * 128 + ((c ^ (r & 7)) << 4));
            size_t aoff = (size_t)(m0 + r) * K + k0 + c * 8;
            cp16(st + PL_AH + doff, Ah + aoff, true);
            cp16(st + PL_AL + doff, Al + aoff, true);
            bool bv = (n0 + r) < N;
            int  br = bv ? (n0 + r) : 0;
            size_t boff = (size_t)br * K + k0 + c * 8;
            cp16(st + PL_BH + doff, Bh + boff, bv);
            cp16(st + PL_BL + doff, Bl + boff, bv);
        }
        cp_commit();
    };

    const int nIt = K >> 6;
    load_tile(0, 0);

    for (int it = 0; it < nIt; it++) {
        if (it + 1 < nIt) {
            load_tile(it + 1, (it + 1) & 1);
            cp_wait<1>();
        } else {
            cp_wait<0>();
        }
        __syncthreads();

        uint32_t st = sbase + (it & 1) * STG_BYTES;
        #pragma unroll
        for (int ks = 0; ks < 4; ks++) {
            uint32_t ah[4][4], al[4][4], bh[2][4], bl[2][4];
            #pragma unroll
            for (int nh = 0; nh < 2; nh++) {
                int rr = wn * 32 + nh * 16 + (lane >> 4) * 8 + (lane & 7);
                int kc = ks * 2 + ((lane >> 3) & 1);
                uint32_t off = (uint32_t)(rr * 128 + ((kc ^ (rr & 7)) << 4));
                ldsm4(bh[nh][0], bh[nh][1], bh[nh][2], bh[nh][3], st + PL_BH + off);
                ldsm4(bl[nh][0], bl[nh][1], bl[nh][2], bl[nh][3], st + PL_BL + off);
            }
            #pragma unroll
            for (int mt = 0; mt < 4; mt++) {
                int rr = wm * 64 + mt * 16 + ((lane >> 3) & 1) * 8 + (lane & 7);
                int kc = ks * 2 + (lane >> 4);
                uint32_t off = (uint32_t)(rr * 128 + ((kc ^ (rr & 7)) << 4));
                ldsm4(ah[mt][0], ah[mt][1], ah[mt][2], ah[mt][3], st + PL_AH + off);
                ldsm4(al[mt][0], al[mt][1], al[mt][2], al[mt][3], st + PL_AL + off);
            }
            #pragma unroll
            for (int mt = 0; mt < 4; mt++)
                #pragma unroll
                for (int nt = 0; nt < 4; nt++) {
                    uint32_t b0 = bh[nt >> 1][(nt & 1) * 2];
                    uint32_t b1 = bh[nt >> 1][(nt & 1) * 2 + 1];
                    mma_bf16(acc[mt][nt], ah[mt], b0, b1);
                    mma_bf16(acc[mt][nt], al[mt], b0, b1);
                    mma_bf16(acc[mt][nt], ah[mt],
                             bl[nt >> 1][(nt & 1) * 2], bl[nt >> 1][(nt & 1) * 2 + 1]);
                }
        }
        __syncthreads();
    }

    // epilogue
    #pragma unroll
    for (int mt = 0; mt < 4; mt++) {
        int row = m0 + wm * 64 + mt * 16 + (lane >> 2);
        #pragma unroll
        for (int nt = 0; nt < 4; nt++) {
            int col = n0 + wn * 32 + nt * 8 + (lane & 3) * 2;
            if (col < N) {
                float c0 = acc[mt][nt][0], c1 = acc[mt][nt][1];
                float c2 = acc[mt][nt][2], c3 = acc[mt][nt][3];
                if (EPI == 1) {
                    float b0 = bias[col], b1 = bias[col + 1];
                    c0 += b0; c1 += b1; c2 += b0; c3 += b1;
                    c0 = (c0 >= 0.f) ? c0 : 0.1f * c0;
                    c1 = (c1 >= 0.f) ? c1 : 0.1f * c1;
                    c2 = (c2 >= 0.f) ? c2 : 0.1f * c2;
                    c3 = (c3 >= 0.f) ? c3 : 0.1f * c3;
                    uint32_t h, l;
                    split2(c0, c1, h, l);
                    *(uint32_t*)(Ch + (size_t)row * ldc + col) = h;
                    *(uint32_t*)(Cl + (size_t)row * ldc + col) = l;
                    split2(c2, c3, h, l);
                    *(uint32_t*)(Ch + (size_t)(row + 8) * ldc + col) = h;
                    *(uint32_t*)(Cl + (size_t)(row + 8) * ldc + col) = l;
                } else {
                    *(float2*)(C + (size_t)row * ldc + col)       = make_float2(c0, c1);
                    *(float2*)(C + (size_t)(row + 8) * ldc + col) = make_float2(c2, c3);
                }
            }
        }
    }
}

// ---------------- launch ----------------
static inline void* sym_addr(const void* sym) {
    void* p = nullptr;
    cudaGetSymbolAddress(&p, sym);
    return p;
}

extern "C" void kernel_launch(void* const* d_in, const int* in_sizes, int n_in,
                              void* d_out, int out_size)
{
    const float* adj = (const float*)d_in[0];
    const float* x   = (const float*)d_in[1];
    const float* W1  = (const float*)d_in[2];
    const float* W2  = (const float*)d_in[3];
    const float* Wm1 = (const float*)d_in[4];
    const float* Wm2 = (const float*)d_in[5];
    const float* Wm3 = (const float*)d_in[6];
    const float* Wt  = (const float*)d_in[7];
    const float* bt  = (const float*)d_in[8];

    float* out = (float*)d_out;
    float* out_pred = out;
    float* out_x1   = out + (size_t)NN * NN;
    float* out_x2   = out_x1 + (size_t)NN * H1;
    float* out_z    = out_x2 + (size_t)NN * H2;

    float* t1 = (float*)sym_addr(g_t1);
    float* t2 = (float*)sym_addr(g_t2);
    float* tm = (float*)sym_addr(g_tm);
    __nv_bfloat16* xh  = (__nv_bfloat16*)sym_addr(g_xh);
    __nv_bfloat16* xl  = (__nv_bfloat16*)sym_addr(g_xl);
    __nv_bfloat16* x1h = (__nv_bfloat16*)sym_addr(g_x1h);
    __nv_bfloat16* x1l = (__nv_bfloat16*)sym_addr(g_x1l);
    __nv_bfloat16* x2h = (__nv_bfloat16*)sym_addr(g_x2h);
    __nv_bfloat16* x2l = (__nv_bfloat16*)sym_addr(g_x2l);
    __nv_bfloat16* zh  = (__nv_bfloat16*)sym_addr(g_zh);
    __nv_bfloat16* zl  = (__nv_bfloat16*)sym_addr(g_zl);
    __nv_bfloat16* tzh = (__nv_bfloat16*)sym_addr(g_tzh);
    __nv_bfloat16* tzl = (__nv_bfloat16*)sym_addr(g_tzl);
    __nv_bfloat16* W1h = (__nv_bfloat16*)sym_addr(g_W1h);
    __nv_bfloat16* W1l = (__nv_bfloat16*)sym_addr(g_W1l);
    __nv_bfloat16* W2h = (__nv_bfloat16*)sym_addr(g_W2h);
    __nv_bfloat16* W2l = (__nv_bfloat16*)sym_addr(g_W2l);
    __nv_bfloat16* Wmh = (__nv_bfloat16*)sym_addr(g_Wmh);
    __nv_bfloat16* Wml = (__nv_bfloat16*)sym_addr(g_Wml);
    __nv_bfloat16* Wth = (__nv_bfloat16*)sym_addr(g_Wth);
    __nv_bfloat16* Wtl = (__nv_bfloat16*)sym_addr(g_Wtl);

    cudaFuncSetAttribute((const void*)gemm3<0>,
                         cudaFuncAttributeMaxDynamicSharedMemorySize, SMEM_BYTES);
    cudaFuncSetAttribute((const void*)gemm3<1>,
                         cudaFuncAttributeMaxDynamicSharedMemorySize, SMEM_BYTES);

    // 0. split static inputs into bf16 hi/lo planes
    auto launch_split = [&](const float* src, __nv_bfloat16* h, __nv_bfloat16* l, int n) {
        int nq = n / 4;
        split_kernel<<<(nq + 255) / 256, 256>>>((const float4*)src,
                                                (uint32_t*)h, (uint32_t*)l, nq);
    };
    launch_split(x,   xh,  xl,  NN * IN_DIM);
    launch_split(W1,  W1h, W1l, H1 * IN_DIM);
    launch_split(W2,  W2h, W2l, H2 * H1);
    launch_split(Wm1, Wmh,            Wml,            64 * H2);
    launch_split(Wm2, Wmh + 64 * H2,  Wml + 64 * H2,  64 * H2);
    launch_split(Wm3, Wmh + 128 * H2, Wml + 128 * H2, 64 * H2);
    launch_split(Wt,  Wth, Wtl, ZD * ZD);

    // 1. sparsify adj -> CSR
    build_csr_kernel<<<NN / 8, 256>>>(adj);

    // 2. t1 = x @ W1^T
    gemm3<0><<<dim3(H1 / GBN, NN / GBM), 256, SMEM_BYTES>>>(
        xh, xl, W1h, W1l, nullptr, t1, nullptr, nullptr, NN, H1, IN_DIM, H1);
    // 3. x1 = relu(adj @ t1) -> planes; out_x1 = sigmoid
    spmm_kernel<1><<<dim3(NN, H1 / 256), 256>>>(t1, H1, out_x1, x1h, x1l);
    // 4. t2 = x1 @ W2^T
    gemm3<0><<<dim3(H2 / GBN, NN / GBM), 256, SMEM_BYTES>>>(
        x1h, x1l, W2h, W2l, nullptr, t2, nullptr, nullptr, NN, H2, H1, H2);
    // 5. x2 planes; out_x2 = sigmoid
    spmm_kernel<1><<<dim3(NN, 1), 256>>>(t2, H2, out_x2, x2h, x2l);
    // 6. tm = x2 @ Wm^T   (Wm = concat of Wm1/2/3, N=192)
    gemm3<0><<<dim3(2, NN / GBM), 256, SMEM_BYTES>>>(
        x2h, x2l, Wmh, Wml, nullptr, tm, nullptr, nullptr, NN, ZD, H2, ZD);
    // 7. z = adj @ tm -> out_z fp32 + planes
    spmm_kernel<0><<<dim3(NN, 1), 256>>>(tm, ZD, out_z, zh, zl);
    // 8. tz = leaky(z @ Wt^T + bt) -> planes directly
    gemm3<1><<<dim3(2, NN / GBM), 256, SMEM_BYTES>>>(
        zh, zl, Wth, Wtl, bt, nullptr, tzh, tzl, NN, ZD, ZD, ZD);
    // 9. pred = z @ tz^T
    gemm3<0><<<dim3(NN / GBN, NN / GBM), 256, SMEM_BYTES>>>(
        zh, zl, tzh, tzl, nullptr, out_pred, nullptr, nullptr, NN, NN, ZD, NN);

    (void)in_sizes; (void)n_in; (void)out_size;
}

// round 6
// speedup vs baseline: 2.6288x; 1.0210x over previous
#include <cuda_runtime.h>
#include <cuda_bf16.h>
#include <math.h>
#include <stdint.h>

// Problem dims
#define NN      8192
#define IN_DIM  1024
#define H1      512
#define H2      256
#define ZD      192
#define CAP     192

// ---------------- device scratch ----------------
__device__ float g_t1[NN * H1];
__device__ float g_t2[NN * H2];
__device__ float g_tm[NN * ZD];
__device__ __nv_bfloat16 g_xh [NN * IN_DIM];
__device__ __nv_bfloat16 g_xl [NN * IN_DIM];
__device__ __nv_bfloat16 g_x1h[NN * H1];
__device__ __nv_bfloat16 g_x1l[NN * H1];
__device__ __nv_bfloat16 g_x2h[NN * H2];
__device__ __nv_bfloat16 g_x2l[NN * H2];
__device__ __nv_bfloat16 g_zh [NN * ZD];
__device__ __nv_bfloat16 g_zl [NN * ZD];
__device__ __nv_bfloat16 g_tzh[NN * ZD];
__device__ __nv_bfloat16 g_tzl[NN * ZD];
__device__ __nv_bfloat16 g_W1h[H1 * IN_DIM];
__device__ __nv_bfloat16 g_W1l[H1 * IN_DIM];
__device__ __nv_bfloat16 g_W2h[H2 * H1];
__device__ __nv_bfloat16 g_W2l[H2 * H1];
__device__ __nv_bfloat16 g_Wmh[ZD * H2];
__device__ __nv_bfloat16 g_Wml[ZD * H2];
__device__ __nv_bfloat16 g_Wth[ZD * ZD];
__device__ __nv_bfloat16 g_Wtl[ZD * ZD];
__device__ float g_vals[NN * CAP];
__device__ int   g_cols[NN * CAP];
__device__ int   g_cnt [NN];

// ---------------- helpers ----------------
__device__ __forceinline__ void split2(float v0, float v1, uint32_t& hi, uint32_t& lo) {
    __nv_bfloat16 h0 = __float2bfloat16_rn(v0);
    __nv_bfloat16 h1 = __float2bfloat16_rn(v1);
    __nv_bfloat16 l0 = __float2bfloat16_rn(v0 - __bfloat162float(h0));
    __nv_bfloat16 l1 = __float2bfloat16_rn(v1 - __bfloat162float(h1));
    hi = (uint32_t)__bfloat16_as_ushort(h0) | ((uint32_t)__bfloat16_as_ushort(h1) << 16);
    lo = (uint32_t)__bfloat16_as_ushort(l0) | ((uint32_t)__bfloat16_as_ushort(l1) << 16);
}

__device__ __forceinline__ void ldsm4(uint32_t& r0, uint32_t& r1, uint32_t& r2,
                                      uint32_t& r3, uint32_t addr) {
    asm volatile("ldmatrix.sync.aligned.m8n8.x4.shared.b16 {%0,%1,%2,%3}, [%4];"
                 : "=r"(r0), "=r"(r1), "=r"(r2), "=r"(r3) : "r"(addr));
}

__device__ __forceinline__ void mma_bf16(float (&d)[4], const uint32_t (&a)[4],
                                         uint32_t b0, uint32_t b1) {
    asm volatile(
        "mma.sync.aligned.m16n8k16.row.col.f32.bf16.bf16.f32 "
        "{%0,%1,%2,%3}, {%4,%5,%6,%7}, {%8,%9}, {%0,%1,%2,%3};"
        : "+f"(d[0]), "+f"(d[1]), "+f"(d[2]), "+f"(d[3])
        : "r"(a[0]), "r"(a[1]), "r"(a[2]), "r"(a[3]), "r"(b0), "r"(b1));
}

__device__ __forceinline__ void cp16(uint32_t dst, const void* src, bool v) {
    int sz = v ? 16 : 0;
    asm volatile("cp.async.cg.shared.global [%0], [%1], 16, %2;\n"
                 :: "r"(dst), "l"(src), "r"(sz) : "memory");
}
__device__ __forceinline__ void cp_commit() {
    asm volatile("cp.async.commit_group;" ::: "memory");
}
template <int n>
__device__ __forceinline__ void cp_wait() {
    asm volatile("cp.async.wait_group %0;" :: "n"(n) : "memory");
}

// ---------------- split fp32 -> bf16 hi/lo planes ----------------
__global__ void split_kernel(const float4* __restrict__ src,
                             uint32_t* __restrict__ hi, uint32_t* __restrict__ lo,
                             int nq) {
    int i = blockIdx.x * 256 + threadIdx.x;
    if (i >= nq) return;
    float4 v = src[i];
    uint32_t h0, l0, h1, l1;
    split2(v.x, v.y, h0, l0);
    split2(v.z, v.w, h1, l1);
    hi[i * 2]     = h0; hi[i * 2 + 1] = h1;
    lo[i * 2]     = l0; lo[i * 2 + 1] = l1;
}

// ---------------- CSR build ----------------
__global__ void build_csr_kernel(const float* __restrict__ adj) {
    int row  = blockIdx.x * (blockDim.x >> 5) + (threadIdx.x >> 5);
    int lane = threadIdx.x & 31;
    if (row >= NN) return;
    const float* arow = adj + (size_t)row * NN;
    int cnt = 0;
    for (int c0 = 0; c0 < NN; c0 += 128) {
        float4 v = *(const float4*)(arow + c0 + lane * 4);
        unsigned m = (v.x != 0.f ? 1u : 0u) | (v.y != 0.f ? 2u : 0u)
                   | (v.z != 0.f ? 4u : 0u) | (v.w != 0.f ? 8u : 0u);
        int c = __popc(m);
        int s = c;
        #pragma unroll
        for (int d = 1; d < 32; d <<= 1) {
            int t = __shfl_up_sync(0xffffffffu, s, d);
            if (lane >= d) s += t;
        }
        int pos = cnt + s - c;
        int base = c0 + lane * 4;
        float vv[4] = {v.x, v.y, v.z, v.w};
        #pragma unroll
        for (int e = 0; e < 4; e++) {
            if ((m >> e) & 1u) {
                if (pos < CAP) {
                    g_cols[row * CAP + pos] = base + e;
                    g_vals[row * CAP + pos] = vv[e];
                }
                pos++;
            }
        }
        cnt += __shfl_sync(0xffffffffu, s, 31);
    }
    if (lane == 0) g_cnt[row] = (cnt < CAP) ? cnt : CAP;
}

// ---------------- SpMM ----------------
template <int MODE>
__global__ void __launch_bounds__(256) spmm_kernel(
    const float* __restrict__ X, int ncols,
    float* __restrict__ out_f32,
    __nv_bfloat16* __restrict__ hi, __nv_bfloat16* __restrict__ lo)
{
    int row = blockIdx.x;
    int col = blockIdx.y * 256 + threadIdx.x;
    if (col >= ncols) return;
    int cnt = g_cnt[row];
    const int*   cols = g_cols + row * CAP;
    const float* vals = g_vals + row * CAP;

    float a0 = 0.f, a1 = 0.f, a2 = 0.f, a3 = 0.f;
    int j = 0;
    for (; j + 4 <= cnt; j += 4) {
        int   c0 = cols[j+0], c1 = cols[j+1], c2 = cols[j+2], c3 = cols[j+3];
        float v0 = vals[j+0], v1 = vals[j+1], v2 = vals[j+2], v3 = vals[j+3];
        a0 += v0 * X[(size_t)c0 * ncols + col];
        a1 += v1 * X[(size_t)c1 * ncols + col];
        a2 += v2 * X[(size_t)c2 * ncols + col];
        a3 += v3 * X[(size_t)c3 * ncols + col];
    }
    for (; j < cnt; j++)
        a0 += vals[j] * X[(size_t)cols[j] * ncols + col];
    float acc = (a0 + a1) + (a2 + a3);

    size_t o = (size_t)row * ncols + col;
    float r = (MODE == 1) ? (acc > 0.f ? acc : 0.f) : acc;
    __nv_bfloat16 h = __float2bfloat16_rn(r);
    hi[o] = h;
    lo[o] = __float2bfloat16_rn(r - __bfloat162float(h));
    out_f32[o] = (MODE == 1) ? (1.0f / (1.0f + __expf(-r))) : acc;
}

// ---------------- bf16x3 mma.sync GEMM ----------------
// 128-thread CTA, 4 warps (2x2), warp tile 64x64, CTA tile 128x128, GBK=32.
// smem/stage: 4 planes x (128 rows x 32 bf16) = 32KB; 2 stages = 64KB.
// -> 2 CTAs/SM for cross-CTA latency hiding.
#define GBM 128
#define GBN 128
#define GBK 32
#define PLANE_B   8192           // bytes per plane per stage
#define STG_BYTES 32768
#define SMEM_BYTES (2 * STG_BYTES)
#define PL_AH 0
#define PL_AL 8192
#define PL_BH 16384
#define PL_BL 24576

// swizzled byte offset inside a 128x32 bf16 plane (64B rows, 4 chunks)
__device__ __forceinline__ uint32_t sw_off(int r, int kc) {
    return (uint32_t)(r * 64 + ((kc ^ ((r >> 1) & 3)) << 4));
}

template <int EPI>
__global__ void __launch_bounds__(128, 2) gemm3(
    const __nv_bfloat16* __restrict__ Ah, const __nv_bfloat16* __restrict__ Al,
    const __nv_bfloat16* __restrict__ Bh, const __nv_bfloat16* __restrict__ Bl,
    const float* __restrict__ bias, float* __restrict__ C,
    __nv_bfloat16* __restrict__ Ch, __nv_bfloat16* __restrict__ Cl,
    int M, int N, int K, int ldc)
{
    extern __shared__ uint8_t smem[];
    const uint32_t sbase = (uint32_t)__cvta_generic_to_shared(smem);

    const int tid  = threadIdx.x;
    const int lane = tid & 31;
    const int wid  = tid >> 5;
    const int wm   = wid & 1;            // 2 warps in M, 64 rows each
    const int wn   = wid >> 1;           // 2 warps in N, 64 cols each
    const int m0   = blockIdx.y * GBM;
    const int n0   = blockIdx.x * GBN;

    float acc[4][8][4];
    #pragma unroll
    for (int i = 0; i < 4; i++)
        #pragma unroll
        for (int j = 0; j < 8; j++)
            #pragma unroll
            for (int q = 0; q < 4; q++) acc[i][j][q] = 0.f;

    // loader: 512 chunks/plane, 4 planes -> 16 cp.async per thread
    auto load_tile = [&](int it, int s) {
        int k0 = it * GBK;
        uint32_t st = sbase + s * STG_BYTES;
        #pragma unroll
        for (int i = 0; i < 4; i++) {
            int f = tid + i * 128;       // 0..511 chunk index
            int r = f >> 2, c = f & 3;
            uint32_t doff = sw_off(r, c);
            size_t aoff = (size_t)(m0 + r) * K + k0 + c * 8;
            cp16(st + PL_AH + doff, Ah + aoff, true);
            cp16(st + PL_AL + doff, Al + aoff, true);
            bool bv = (n0 + r) < N;
            int  br = bv ? (n0 + r) : 0;
            size_t boff = (size_t)br * K + k0 + c * 8;
            cp16(st + PL_BH + doff, Bh + boff, bv);
            cp16(st + PL_BL + doff, Bl + boff, bv);
        }
        cp_commit();
    };

    const int nIt = K / GBK;
    load_tile(0, 0);

    for (int it = 0; it < nIt; it++) {
        if (it + 1 < nIt) {
            load_tile(it + 1, (it + 1) & 1);
            cp_wait<1>();
        } else {
            cp_wait<0>();
        }
        __syncthreads();

        uint32_t st = sbase + (it & 1) * STG_BYTES;
        #pragma unroll
        for (int ks = 0; ks < 2; ks++) {
            uint32_t ah[4][4], al[4][4], bh[4][4], bl[4][4];
            // B fragments: 4 groups of 16 n-rows covering 64 cols
            #pragma unroll
            for (int nh = 0; nh < 4; nh++) {
                int rr = wn * 64 + nh * 16 + (lane >> 4) * 8 + (lane & 7);
                int kc = ks * 2 + ((lane >> 3) & 1);
                uint32_t off = sw_off(rr, kc);
                ldsm4(bh[nh][0], bh[nh][1], bh[nh][2], bh[nh][3], st + PL_BH + off);
                ldsm4(bl[nh][0], bl[nh][1], bl[nh][2], bl[nh][3], st + PL_BL + off);
            }
            // A fragments: 4 m16 tiles covering 64 rows
            #pragma unroll
            for (int mt = 0; mt < 4; mt++) {
                int rr = wm * 64 + mt * 16 + ((lane >> 3) & 1) * 8 + (lane & 7);
                int kc = ks * 2 + (lane >> 4);
                uint32_t off = sw_off(rr, kc);
                ldsm4(ah[mt][0], ah[mt][1], ah[mt][2], ah[mt][3], st + PL_AH + off);
                ldsm4(al[mt][0], al[mt][1], al[mt][2], al[mt][3], st + PL_AL + off);
            }
            #pragma unroll
            for (int mt = 0; mt < 4; mt++)
                #pragma unroll
                for (int nt = 0; nt < 8; nt++) {
                    uint32_t b0 = bh[nt >> 1][(nt & 1) * 2];
                    uint32_t b1 = bh[nt >> 1][(nt & 1) * 2 + 1];
                    mma_bf16(acc[mt][nt], ah[mt], b0, b1);
                    mma_bf16(acc[mt][nt], al[mt], b0, b1);
                    mma_bf16(acc[mt][nt], ah[mt],
                             bl[nt >> 1][(nt & 1) * 2], bl[nt >> 1][(nt & 1) * 2 + 1]);
                }
        }
        __syncthreads();
    }

    // epilogue
    #pragma unroll
    for (int mt = 0; mt < 4; mt++) {
        int row = m0 + wm * 64 + mt * 16 + (lane >> 2);
        #pragma unroll
        for (int nt = 0; nt < 8; nt++) {
            int col = n0 + wn * 64 + nt * 8 + (lane & 3) * 2;
            if (col < N) {
                float c0 = acc[mt][nt][0], c1 = acc[mt][nt][1];
                float c2 = acc[mt][nt][2], c3 = acc[mt][nt][3];
                if (EPI == 1) {
                    float b0 = bias[col], b1 = bias[col + 1];
                    c0 += b0; c1 += b1; c2 += b0; c3 += b1;
                    c0 = (c0 >= 0.f) ? c0 : 0.1f * c0;
                    c1 = (c1 >= 0.f) ? c1 : 0.1f * c1;
                    c2 = (c2 >= 0.f) ? c2 : 0.1f * c2;
                    c3 = (c3 >= 0.f) ? c3 : 0.1f * c3;
                    uint32_t h, l;
                    split2(c0, c1, h, l);
                    *(uint32_t*)(Ch + (size_t)row * ldc + col) = h;
                    *(uint32_t*)(Cl + (size_t)row * ldc + col) = l;
                    split2(c2, c3, h, l);
                    *(uint32_t*)(Ch + (size_t)(row + 8) * ldc + col) = h;
                    *(uint32_t*)(Cl + (size_t)(row + 8) * ldc + col) = l;
                } else {
                    *(float2*)(C + (size_t)row * ldc + col)       = make_float2(c0, c1);
                    *(float2*)(C + (size_t)(row + 8) * ldc + col) = make_float2(c2, c3);
                }
            }
        }
    }
}

// ---------------- launch ----------------
static inline void* sym_addr(const void* sym) {
    void* p = nullptr;
    cudaGetSymbolAddress(&p, sym);
    return p;
}

extern "C" void kernel_launch(void* const* d_in, const int* in_sizes, int n_in,
                              void* d_out, int out_size)
{
    const float* adj = (const float*)d_in[0];
    const float* x   = (const float*)d_in[1];
    const float* W1  = (const float*)d_in[2];
    const float* W2  = (const float*)d_in[3];
    const float* Wm1 = (const float*)d_in[4];
    const float* Wm2 = (const float*)d_in[5];
    const float* Wm3 = (const float*)d_in[6];
    const float* Wt  = (const float*)d_in[7];
    const float* bt  = (const float*)d_in[8];

    float* out = (float*)d_out;
    float* out_pred = out;
    float* out_x1   = out + (size_t)NN * NN;
    float* out_x2   = out_x1 + (size_t)NN * H1;
    float* out_z    = out_x2 + (size_t)NN * H2;

    float* t1 = (float*)sym_addr(g_t1);
    float* t2 = (float*)sym_addr(g_t2);
    float* tm = (float*)sym_addr(g_tm);
    __nv_bfloat16* xh  = (__nv_bfloat16*)sym_addr(g_xh);
    __nv_bfloat16* xl  = (__nv_bfloat16*)sym_addr(g_xl);
    __nv_bfloat16* x1h = (__nv_bfloat16*)sym_addr(g_x1h);
    __nv_bfloat16* x1l = (__nv_bfloat16*)sym_addr(g_x1l);
    __nv_bfloat16* x2h = (__nv_bfloat16*)sym_addr(g_x2h);
    __nv_bfloat16* x2l = (__nv_bfloat16*)sym_addr(g_x2l);
    __nv_bfloat16* zh  = (__nv_bfloat16*)sym_addr(g_zh);
    __nv_bfloat16* zl  = (__nv_bfloat16*)sym_addr(g_zl);
    __nv_bfloat16* tzh = (__nv_bfloat16*)sym_addr(g_tzh);
    __nv_bfloat16* tzl = (__nv_bfloat16*)sym_addr(g_tzl);
    __nv_bfloat16* W1h = (__nv_bfloat16*)sym_addr(g_W1h);
    __nv_bfloat16* W1l = (__nv_bfloat16*)sym_addr(g_W1l);
    __nv_bfloat16* W2h = (__nv_bfloat16*)sym_addr(g_W2h);
    __nv_bfloat16* W2l = (__nv_bfloat16*)sym_addr(g_W2l);
    __nv_bfloat16* Wmh = (__nv_bfloat16*)sym_addr(g_Wmh);
    __nv_bfloat16* Wml = (__nv_bfloat16*)sym_addr(g_Wml);
    __nv_bfloat16* Wth = (__nv_bfloat16*)sym_addr(g_Wth);
    __nv_bfloat16* Wtl = (__nv_bfloat16*)sym_addr(g_Wtl);

    cudaFuncSetAttribute((const void*)gemm3<0>,
                         cudaFuncAttributeMaxDynamicSharedMemorySize, SMEM_BYTES);
    cudaFuncSetAttribute((const void*)gemm3<1>,
                         cudaFuncAttributeMaxDynamicSharedMemorySize, SMEM_BYTES);

    auto launch_split = [&](const float* src, __nv_bfloat16* h, __nv_bfloat16* l, int n) {
        int nq = n / 4;
        split_kernel<<<(nq + 255) / 256, 256>>>((const float4*)src,
                                                (uint32_t*)h, (uint32_t*)l, nq);
    };
    launch_split(x,   xh,  xl,  NN * IN_DIM);
    launch_split(W1,  W1h, W1l, H1 * IN_DIM);
    launch_split(W2,  W2h, W2l, H2 * H1);
    launch_split(Wm1, Wmh,            Wml,            64 * H2);
    launch_split(Wm2, Wmh + 64 * H2,  Wml + 64 * H2,  64 * H2);
    launch_split(Wm3, Wmh + 128 * H2, Wml + 128 * H2, 64 * H2);
    launch_split(Wt,  Wth, Wtl, ZD * ZD);

    build_csr_kernel<<<NN / 8, 256>>>(adj);

    // t1 = x @ W1^T
    gemm3<0><<<dim3(H1 / GBN, NN / GBM), 128, SMEM_BYTES>>>(
        xh, xl, W1h, W1l, nullptr, t1, nullptr, nullptr, NN, H1, IN_DIM, H1);
    // x1 planes + sigmoid
    spmm_kernel<1><<<dim3(NN, H1 / 256), 256>>>(t1, H1, out_x1, x1h, x1l);
    // t2 = x1 @ W2^T
    gemm3<0><<<dim3(H2 / GBN, NN / GBM), 128, SMEM_BYTES>>>(
        x1h, x1l, W2h, W2l, nullptr, t2, nullptr, nullptr, NN, H2, H1, H2);
    // x2 planes + sigmoid
    spmm_kernel<1><<<dim3(NN, 1), 256>>>(t2, H2, out_x2, x2h, x2l);
    // tm = x2 @ Wm^T
    gemm3<0><<<dim3(2, NN / GBM), 128, SMEM_BYTES>>>(
        x2h, x2l, Wmh, Wml, nullptr, tm, nullptr, nullptr, NN, ZD, H2, ZD);
    // z = adj @ tm
    spmm_kernel<0><<<dim3(NN, 1), 256>>>(tm, ZD, out_z, zh, zl);
    // tz = leaky(z @ Wt^T + bt) -> planes
    gemm3<1><<<dim3(2, NN / GBM), 128, SMEM_BYTES>>>(
        zh, zl, Wth, Wtl, bt, nullptr, tzh, tzl, NN, ZD, ZD, ZD);
    // pred = z @ tz^T
    gemm3<0><<<dim3(NN / GBN, NN / GBM), 128, SMEM_BYTES>>>(
        zh, zl, tzh, tzl, nullptr, out_pred, nullptr, nullptr, NN, NN, ZD, NN);

    (void)in_sizes; (void)n_in; (void)out_size;
}

// round 7
// speedup vs baseline: 2.6450x; 1.0062x over previous
#include <cuda_runtime.h>
#include <cuda_bf16.h>
#include <math.h>
#include <stdint.h>

// Problem dims
#define NN      8192
#define IN_DIM  1024
#define H1      512
#define H2      256
#define ZD      192
#define CAP     192

// ---------------- device scratch ----------------
__device__ float g_t1[NN * H1];
__device__ float g_t2[NN * H2];
__device__ float g_tm[NN * ZD];
__device__ __nv_bfloat16 g_xh [NN * IN_DIM];
__device__ __nv_bfloat16 g_xl [NN * IN_DIM];
__device__ __nv_bfloat16 g_x1h[NN * H1];
__device__ __nv_bfloat16 g_x1l[NN * H1];
__device__ __nv_bfloat16 g_x2h[NN * H2];
__device__ __nv_bfloat16 g_x2l[NN * H2];
__device__ __nv_bfloat16 g_zh [NN * ZD];
__device__ __nv_bfloat16 g_zl [NN * ZD];
__device__ __nv_bfloat16 g_tzh[NN * ZD];
__device__ __nv_bfloat16 g_tzl[NN * ZD];
__device__ __nv_bfloat16 g_W1h[H1 * IN_DIM];
__device__ __nv_bfloat16 g_W1l[H1 * IN_DIM];
__device__ __nv_bfloat16 g_W2h[H2 * H1];
__device__ __nv_bfloat16 g_W2l[H2 * H1];
__device__ __nv_bfloat16 g_Wmh[ZD * H2];
__device__ __nv_bfloat16 g_Wml[ZD * H2];
__device__ __nv_bfloat16 g_Wth[ZD * ZD];
__device__ __nv_bfloat16 g_Wtl[ZD * ZD];
__device__ float g_vals[NN * CAP];
__device__ int   g_cols[NN * CAP];
__device__ int   g_cnt [NN];

// ---------------- helpers ----------------
__device__ __forceinline__ void split2(float v0, float v1, uint32_t& hi, uint32_t& lo) {
    __nv_bfloat16 h0 = __float2bfloat16_rn(v0);
    __nv_bfloat16 h1 = __float2bfloat16_rn(v1);
    __nv_bfloat16 l0 = __float2bfloat16_rn(v0 - __bfloat162float(h0));
    __nv_bfloat16 l1 = __float2bfloat16_rn(v1 - __bfloat162float(h1));
    hi = (uint32_t)__bfloat16_as_ushort(h0) | ((uint32_t)__bfloat16_as_ushort(h1) << 16);
    lo = (uint32_t)__bfloat16_as_ushort(l0) | ((uint32_t)__bfloat16_as_ushort(l1) << 16);
}

__device__ __forceinline__ void ldsm4(uint32_t& r0, uint32_t& r1, uint32_t& r2,
                                      uint32_t& r3, uint32_t addr) {
    asm volatile("ldmatrix.sync.aligned.m8n8.x4.shared.b16 {%0,%1,%2,%3}, [%4];"
                 : "=r"(r0), "=r"(r1), "=r"(r2), "=r"(r3) : "r"(addr));
}

__device__ __forceinline__ void mma_bf16(float (&d)[4], const uint32_t (&a)[4],
                                         uint32_t b0, uint32_t b1) {
    asm volatile(
        "mma.sync.aligned.m16n8k16.row.col.f32.bf16.bf16.f32 "
        "{%0,%1,%2,%3}, {%4,%5,%6,%7}, {%8,%9}, {%0,%1,%2,%3};"
        : "+f"(d[0]), "+f"(d[1]), "+f"(d[2]), "+f"(d[3])
        : "r"(a[0]), "r"(a[1]), "r"(a[2]), "r"(a[3]), "r"(b0), "r"(b1));
}

__device__ __forceinline__ void cp16(uint32_t dst, const void* src, bool v) {
    int sz = v ? 16 : 0;
    asm volatile("cp.async.cg.shared.global [%0], [%1], 16, %2;\n"
                 :: "r"(dst), "l"(src), "r"(sz) : "memory");
}
__device__ __forceinline__ void cp_commit() {
    asm volatile("cp.async.commit_group;" ::: "memory");
}
template <int n>
__device__ __forceinline__ void cp_wait() {
    asm volatile("cp.async.wait_group %0;" :: "n"(n) : "memory");
}

// ---------------- split fp32 -> bf16 hi/lo planes ----------------
__global__ void split_kernel(const float4* __restrict__ src,
                             uint32_t* __restrict__ hi, uint32_t* __restrict__ lo,
                             int nq) {
    int i = blockIdx.x * 256 + threadIdx.x;
    if (i >= nq) return;
    float4 v = src[i];
    uint32_t h0, l0, h1, l1;
    split2(v.x, v.y, h0, l0);
    split2(v.z, v.w, h1, l1);
    hi[i * 2]     = h0; hi[i * 2 + 1] = h1;
    lo[i * 2]     = l0; lo[i * 2 + 1] = l1;
}

// ---------------- CSR build ----------------
__global__ void build_csr_kernel(const float* __restrict__ adj) {
    int row  = blockIdx.x * (blockDim.x >> 5) + (threadIdx.x >> 5);
    int lane = threadIdx.x & 31;
    if (row >= NN) return;
    const float* arow = adj + (size_t)row * NN;
    int cnt = 0;
    for (int c0 = 0; c0 < NN; c0 += 128) {
        float4 v = *(const float4*)(arow + c0 + lane * 4);
        unsigned m = (v.x != 0.f ? 1u : 0u) | (v.y != 0.f ? 2u : 0u)
                   | (v.z != 0.f ? 4u : 0u) | (v.w != 0.f ? 8u : 0u);
        int c = __popc(m);
        int s = c;
        #pragma unroll
        for (int d = 1; d < 32; d <<= 1) {
            int t = __shfl_up_sync(0xffffffffu, s, d);
            if (lane >= d) s += t;
        }
        int pos = cnt + s - c;
        int base = c0 + lane * 4;
        float vv[4] = {v.x, v.y, v.z, v.w};
        #pragma unroll
        for (int e = 0; e < 4; e++) {
            if ((m >> e) & 1u) {
                if (pos < CAP) {
                    g_cols[row * CAP + pos] = base + e;
                    g_vals[row * CAP + pos] = vv[e];
                }
                pos++;
            }
        }
        cnt += __shfl_sync(0xffffffffu, s, 31);
    }
    if (lane == 0) g_cnt[row] = (cnt < CAP) ? cnt : CAP;
}

// ---------------- SpMM ----------------
template <int MODE>
__global__ void __launch_bounds__(256) spmm_kernel(
    const float* __restrict__ X, int ncols,
    float* __restrict__ out_f32,
    __nv_bfloat16* __restrict__ hi, __nv_bfloat16* __restrict__ lo)
{
    int row = blockIdx.x;
    int col = blockIdx.y * 256 + threadIdx.x;
    if (col >= ncols) return;
    int cnt = g_cnt[row];
    const int*   cols = g_cols + row * CAP;
    const float* vals = g_vals + row * CAP;

    float a0 = 0.f, a1 = 0.f, a2 = 0.f, a3 = 0.f;
    int j = 0;
    for (; j + 4 <= cnt; j += 4) {
        int   c0 = cols[j+0], c1 = cols[j+1], c2 = cols[j+2], c3 = cols[j+3];
        float v0 = vals[j+0], v1 = vals[j+1], v2 = vals[j+2], v3 = vals[j+3];
        a0 += v0 * X[(size_t)c0 * ncols + col];
        a1 += v1 * X[(size_t)c1 * ncols + col];
        a2 += v2 * X[(size_t)c2 * ncols + col];
        a3 += v3 * X[(size_t)c3 * ncols + col];
    }
    for (; j < cnt; j++)
        a0 += vals[j] * X[(size_t)cols[j] * ncols + col];
    float acc = (a0 + a1) + (a2 + a3);

    size_t o = (size_t)row * ncols + col;
    float r = (MODE == 1) ? (acc > 0.f ? acc : 0.f) : acc;
    __nv_bfloat16 h = __float2bfloat16_rn(r);
    hi[o] = h;
    lo[o] = __float2bfloat16_rn(r - __bfloat162float(h));
    out_f32[o] = (MODE == 1) ? (1.0f / (1.0f + __expf(-r))) : acc;
}

// ---------------- bf16x3 mma.sync GEMM, pipelined ----------------
// 128-thread CTA, 4 warps (2x2), warp tile 64x64, CTA 128x128, GBK=32.
// 3-stage cp.async pipeline (3 x 32KB = 96KB) + register fragment prefetch.
#define GBM 128
#define GBN 128
#define GBK 32
#define STG_BYTES 32768
#define NSTAGE 3
#define SMEM_BYTES (NSTAGE * STG_BYTES)
#define PL_AH 0
#define PL_AL 8192
#define PL_BH 16384
#define PL_BL 24576

// swizzled byte offset inside a 128x32 bf16 plane (64B rows, 4 chunks)
__device__ __forceinline__ uint32_t sw_off(int r, int kc) {
    return (uint32_t)(r * 64 + ((kc ^ ((r >> 1) & 3)) << 4));
}

template <int EPI>
__global__ void __launch_bounds__(128, 2) gemm3(
    const __nv_bfloat16* __restrict__ Ah, const __nv_bfloat16* __restrict__ Al,
    const __nv_bfloat16* __restrict__ Bh, const __nv_bfloat16* __restrict__ Bl,
    const float* __restrict__ bias, float* __restrict__ C,
    __nv_bfloat16* __restrict__ Ch, __nv_bfloat16* __restrict__ Cl,
    int M, int N, int K, int ldc)
{
    extern __shared__ uint8_t smem[];
    const uint32_t sbase = (uint32_t)__cvta_generic_to_shared(smem);

    const int tid  = threadIdx.x;
    const int lane = tid & 31;
    const int wid  = tid >> 5;
    const int wm   = wid & 1;
    const int wn   = wid >> 1;
    const int m0   = blockIdx.y * GBM;
    const int n0   = blockIdx.x * GBN;

    float acc[4][8][4];
    #pragma unroll
    for (int i = 0; i < 4; i++)
        #pragma unroll
        for (int j = 0; j < 8; j++)
            #pragma unroll
            for (int q = 0; q < 4; q++) acc[i][j][q] = 0.f;

    auto load_tile = [&](int it, int s) {
        int k0 = it * GBK;
        uint32_t st = sbase + s * STG_BYTES;
        #pragma unroll
        for (int i = 0; i < 4; i++) {
            int f = tid + i * 128;
            int r = f >> 2, c = f & 3;
            uint32_t doff = sw_off(r, c);
            size_t aoff = (size_t)(m0 + r) * K + k0 + c * 8;
            cp16(st + PL_AH + doff, Ah + aoff, true);
            cp16(st + PL_AL + doff, Al + aoff, true);
            bool bv = (n0 + r) < N;
            int  br = bv ? (n0 + r) : 0;
            size_t boff = (size_t)br * K + k0 + c * 8;
            cp16(st + PL_BH + doff, Bh + boff, bv);
            cp16(st + PL_BL + doff, Bl + boff, bv);
        }
        cp_commit();
    };

    // fragment loaders
    auto ldA = [&](uint32_t st, int ks, uint32_t (&ah)[4][4], uint32_t (&al)[4][4]) {
        #pragma unroll
        for (int mt = 0; mt < 4; mt++) {
            int rr = wm * 64 + mt * 16 + ((lane >> 3) & 1) * 8 + (lane & 7);
            int kc = ks * 2 + (lane >> 4);
            uint32_t off = sw_off(rr, kc);
            ldsm4(ah[mt][0], ah[mt][1], ah[mt][2], ah[mt][3], st + PL_AH + off);
            ldsm4(al[mt][0], al[mt][1], al[mt][2], al[mt][3], st + PL_AL + off);
        }
    };
    auto ldB = [&](uint32_t st, int ks, int g, uint32_t (&bh)[4], uint32_t (&bl)[4]) {
        int rr = wn * 64 + g * 16 + (lane >> 4) * 8 + (lane & 7);
        int kc = ks * 2 + ((lane >> 3) & 1);
        uint32_t off = sw_off(rr, kc);
        ldsm4(bh[0], bh[1], bh[2], bh[3], st + PL_BH + off);
        ldsm4(bl[0], bl[1], bl[2], bl[3], st + PL_BL + off);
    };
    auto mma_group = [&](int g, uint32_t (&ah)[4][4], uint32_t (&al)[4][4],
                         uint32_t (&bh)[4], uint32_t (&bl)[4]) {
        #pragma unroll
        for (int h = 0; h < 2; h++) {
            int nt = g * 2 + h;
            #pragma unroll
            for (int mt = 0; mt < 4; mt++) {
                mma_bf16(acc[mt][nt], ah[mt], bh[h * 2], bh[h * 2 + 1]);
                mma_bf16(acc[mt][nt], al[mt], bh[h * 2], bh[h * 2 + 1]);
                mma_bf16(acc[mt][nt], ah[mt], bl[h * 2], bl[h * 2 + 1]);
            }
        }
    };

    const int nIt = K / GBK;
    load_tile(0, 0);
    if (nIt > 1) load_tile(1, 1);

    for (int it = 0; it < nIt; it++) {
        if (it + 1 < nIt) cp_wait<1>(); else cp_wait<0>();
        __syncthreads();
        if (it + 2 < nIt) load_tile(it + 2, (it + 2) % NSTAGE);

        uint32_t st = sbase + (it % NSTAGE) * STG_BYTES;

        uint32_t ah0[4][4], al0[4][4], ah1[4][4], al1[4][4];
        uint32_t bhA[4], blA[4], bhB[4], blB[4];

        // ks = 0
        ldA(st, 0, ah0, al0);
        ldB(st, 0, 0, bhA, blA);
        ldB(st, 0, 1, bhB, blB);
        mma_group(0, ah0, al0, bhA, blA);
        ldB(st, 0, 2, bhA, blA);
        mma_group(1, ah0, al0, bhB, blB);
        ldB(st, 0, 3, bhB, blB);
        mma_group(2, ah0, al0, bhA, blA);
        ldA(st, 1, ah1, al1);                 // prefetch A for ks=1
        mma_group(3, ah0, al0, bhB, blB);

        // ks = 1
        ldB(st, 1, 0, bhA, blA);
        ldB(st, 1, 1, bhB, blB);
        mma_group(0, ah1, al1, bhA, blA);
        ldB(st, 1, 2, bhA, blA);
        mma_group(1, ah1, al1, bhB, blB);
        ldB(st, 1, 3, bhB, blB);
        mma_group(2, ah1, al1, bhA, blA);
        mma_group(3, ah1, al1, bhB, blB);

        __syncthreads();
    }

    // epilogue
    #pragma unroll
    for (int mt = 0; mt < 4; mt++) {
        int row = m0 + wm * 64 + mt * 16 + (lane >> 2);
        #pragma unroll
        for (int nt = 0; nt < 8; nt++) {
            int col = n0 + wn * 64 + nt * 8 + (lane & 3) * 2;
            if (col < N) {
                float c0 = acc[mt][nt][0], c1 = acc[mt][nt][1];
                float c2 = acc[mt][nt][2], c3 = acc[mt][nt][3];
                if (EPI == 1) {
                    float b0 = bias[col], b1 = bias[col + 1];
                    c0 += b0; c1 += b1; c2 += b0; c3 += b1;
                    c0 = (c0 >= 0.f) ? c0 : 0.1f * c0;
                    c1 = (c1 >= 0.f) ? c1 : 0.1f * c1;
                    c2 = (c2 >= 0.f) ? c2 : 0.1f * c2;
                    c3 = (c3 >= 0.f) ? c3 : 0.1f * c3;
                    uint32_t h, l;
                    split2(c0, c1, h, l);
                    *(uint32_t*)(Ch + (size_t)row * ldc + col) = h;
                    *(uint32_t*)(Cl + (size_t)row * ldc + col) = l;
                    split2(c2, c3, h, l);
                    *(uint32_t*)(Ch + (size_t)(row + 8) * ldc + col) = h;
                    *(uint32_t*)(Cl + (size_t)(row + 8) * ldc + col) = l;
                } else {
                    *(float2*)(C + (size_t)row * ldc + col)       = make_float2(c0, c1);
                    *(float2*)(C + (size_t)(row + 8) * ldc + col) = make_float2(c2, c3);
                }
            }
        }
    }
}

// ---------------- launch ----------------
static inline void* sym_addr(const void* sym) {
    void* p = nullptr;
    cudaGetSymbolAddress(&p, sym);
    return p;
}

extern "C" void kernel_launch(void* const* d_in, const int* in_sizes, int n_in,
                              void* d_out, int out_size)
{
    const float* adj = (const float*)d_in[0];
    const float* x   = (const float*)d_in[1];
    const float* W1  = (const float*)d_in[2];
    const float* W2  = (const float*)d_in[3];
    const float* Wm1 = (const float*)d_in[4];
    const float* Wm2 = (const float*)d_in[5];
    const float* Wm3 = (const float*)d_in[6];
    const float* Wt  = (const float*)d_in[7];
    const float* bt  = (const float*)d_in[8];

    float* out = (float*)d_out;
    float* out_pred = out;
    float* out_x1   = out + (size_t)NN * NN;
    float* out_x2   = out_x1 + (size_t)NN * H1;
    float* out_z    = out_x2 + (size_t)NN * H2;

    float* t1 = (float*)sym_addr(g_t1);
    float* t2 = (float*)sym_addr(g_t2);
    float* tm = (float*)sym_addr(g_tm);
    __nv_bfloat16* xh  = (__nv_bfloat16*)sym_addr(g_xh);
    __nv_bfloat16* xl  = (__nv_bfloat16*)sym_addr(g_xl);
    __nv_bfloat16* x1h = (__nv_bfloat16*)sym_addr(g_x1h);
    __nv_bfloat16* x1l = (__nv_bfloat16*)sym_addr(g_x1l);
    __nv_bfloat16* x2h = (__nv_bfloat16*)sym_addr(g_x2h);
    __nv_bfloat16* x2l = (__nv_bfloat16*)sym_addr(g_x2l);
    __nv_bfloat16* zh  = (__nv_bfloat16*)sym_addr(g_zh);
    __nv_bfloat16* zl  = (__nv_bfloat16*)sym_addr(g_zl);
    __nv_bfloat16* tzh = (__nv_bfloat16*)sym_addr(g_tzh);
    __nv_bfloat16* tzl = (__nv_bfloat16*)sym_addr(g_tzl);
    __nv_bfloat16* W1h = (__nv_bfloat16*)sym_addr(g_W1h);
    __nv_bfloat16* W1l = (__nv_bfloat16*)sym_addr(g_W1l);
    __nv_bfloat16* W2h = (__nv_bfloat16*)sym_addr(g_W2h);
    __nv_bfloat16* W2l = (__nv_bfloat16*)sym_addr(g_W2l);
    __nv_bfloat16* Wmh = (__nv_bfloat16*)sym_addr(g_Wmh);
    __nv_bfloat16* Wml = (__nv_bfloat16*)sym_addr(g_Wml);
    __nv_bfloat16* Wth = (__nv_bfloat16*)sym_addr(g_Wth);
    __nv_bfloat16* Wtl = (__nv_bfloat16*)sym_addr(g_Wtl);

    cudaFuncSetAttribute((const void*)gemm3<0>,
                         cudaFuncAttributeMaxDynamicSharedMemorySize, SMEM_BYTES);
    cudaFuncSetAttribute((const void*)gemm3<1>,
                         cudaFuncAttributeMaxDynamicSharedMemorySize, SMEM_BYTES);

    auto launch_split = [&](const float* src, __nv_bfloat16* h, __nv_bfloat16* l, int n) {
        int nq = n / 4;
        split_kernel<<<(nq + 255) / 256, 256>>>((const float4*)src,
                                                (uint32_t*)h, (uint32_t*)l, nq);
    };
    launch_split(x,   xh,  xl,  NN * IN_DIM);
    launch_split(W1,  W1h, W1l, H1 * IN_DIM);
    launch_split(W2,  W2h, W2l, H2 * H1);
    launch_split(Wm1, Wmh,            Wml,            64 * H2);
    launch_split(Wm2, Wmh + 64 * H2,  Wml + 64 * H2,  64 * H2);
    launch_split(Wm3, Wmh + 128 * H2, Wml + 128 * H2, 64 * H2);
    launch_split(Wt,  Wth, Wtl, ZD * ZD);

    build_csr_kernel<<<NN / 8, 256>>>(adj);

    // t1 = x @ W1^T
    gemm3<0><<<dim3(H1 / GBN, NN / GBM), 128, SMEM_BYTES>>>(
        xh, xl, W1h, W1l, nullptr, t1, nullptr, nullptr, NN, H1, IN_DIM, H1);
    // x1 planes + sigmoid
    spmm_kernel<1><<<dim3(NN, H1 / 256), 256>>>(t1, H1, out_x1, x1h, x1l);
    // t2 = x1 @ W2^T
    gemm3<0><<<dim3(H2 / GBN, NN / GBM), 128, SMEM_BYTES>>>(
        x1h, x1l, W2h, W2l, nullptr, t2, nullptr, nullptr, NN, H2, H1, H2);
    // x2 planes + sigmoid
    spmm_kernel<1><<<dim3(NN, 1), 256>>>(t2, H2, out_x2, x2h, x2l);
    // tm = x2 @ Wm^T
    gemm3<0><<<dim3(2, NN / GBM), 128, SMEM_BYTES>>>(
        x2h, x2l, Wmh, Wml, nullptr, tm, nullptr, nullptr, NN, ZD, H2, ZD);
    // z = adj @ tm
    spmm_kernel<0><<<dim3(NN, 1), 256>>>(tm, ZD, out_z, zh, zl);
    // tz = leaky(z @ Wt^T + bt) -> planes
    gemm3<1><<<dim3(2, NN / GBM), 128, SMEM_BYTES>>>(
        zh, zl, Wth, Wtl, bt, nullptr, tzh, tzl, NN, ZD, ZD, ZD);
    // pred = z @ tz^T
    gemm3<0><<<dim3(NN / GBN, NN / GBM), 128, SMEM_BYTES>>>(
        zh, zl, tzh, tzl, nullptr, out_pred, nullptr, nullptr, NN, NN, ZD, NN);

    (void)in_sizes; (void)n_in; (void)out_size;
}

// round 8
// speedup vs baseline: 3.2096x; 1.2134x over previous
#include <cuda_runtime.h>
#include <cuda_bf16.h>
#include <cuda_fp16.h>
#include <math.h>
#include <stdint.h>

// Problem dims
#define NN      8192
#define IN_DIM  1024
#define H1      512
#define H2      256
#define ZD      192
#define CAP     192

// ---------------- device scratch ----------------
__device__ float g_t1[NN * H1];
__device__ float g_t2[NN * H2];
__device__ float g_tm[NN * ZD];
__device__ __nv_bfloat16 g_xh [NN * IN_DIM];
__device__ __nv_bfloat16 g_xl [NN * IN_DIM];
__device__ __nv_bfloat16 g_x1h[NN * H1];
__device__ __nv_bfloat16 g_x1l[NN * H1];
__device__ __nv_bfloat16 g_x2h[NN * H2];
__device__ __nv_bfloat16 g_x2l[NN * H2];
__device__ __nv_bfloat16 g_zh [NN * ZD];
__device__ __nv_bfloat16 g_zl [NN * ZD];
__device__ __nv_bfloat16 g_tzh[NN * ZD];
__device__ __nv_bfloat16 g_tzl[NN * ZD];
__device__ __half        g_zf [NN * ZD];
__device__ __half        g_tzf[NN * ZD];
__device__ __nv_bfloat16 g_W1h[H1 * IN_DIM];
__device__ __nv_bfloat16 g_W1l[H1 * IN_DIM];
__device__ __nv_bfloat16 g_W2h[H2 * H1];
__device__ __nv_bfloat16 g_W2l[H2 * H1];
__device__ __nv_bfloat16 g_Wmh[ZD * H2];
__device__ __nv_bfloat16 g_Wml[ZD * H2];
__device__ __nv_bfloat16 g_Wth[ZD * ZD];
__device__ __nv_bfloat16 g_Wtl[ZD * ZD];
__device__ float g_vals[NN * CAP];
__device__ int   g_cols[NN * CAP];
__device__ int   g_cnt [NN];

// ---------------- helpers ----------------
__device__ __forceinline__ void split2(float v0, float v1, uint32_t& hi, uint32_t& lo) {
    __nv_bfloat16 h0 = __float2bfloat16_rn(v0);
    __nv_bfloat16 h1 = __float2bfloat16_rn(v1);
    __nv_bfloat16 l0 = __float2bfloat16_rn(v0 - __bfloat162float(h0));
    __nv_bfloat16 l1 = __float2bfloat16_rn(v1 - __bfloat162float(h1));
    hi = (uint32_t)__bfloat16_as_ushort(h0) | ((uint32_t)__bfloat16_as_ushort(h1) << 16);
    lo = (uint32_t)__bfloat16_as_ushort(l0) | ((uint32_t)__bfloat16_as_ushort(l1) << 16);
}

__device__ __forceinline__ void ldsm4(uint32_t& r0, uint32_t& r1, uint32_t& r2,
                                      uint32_t& r3, uint32_t addr) {
    asm volatile("ldmatrix.sync.aligned.m8n8.x4.shared.b16 {%0,%1,%2,%3}, [%4];"
                 : "=r"(r0), "=r"(r1), "=r"(r2), "=r"(r3) : "r"(addr));
}

__device__ __forceinline__ void mma_bf16(float (&d)[4], const uint32_t (&a)[4],
                                         uint32_t b0, uint32_t b1) {
    asm volatile(
        "mma.sync.aligned.m16n8k16.row.col.f32.bf16.bf16.f32 "
        "{%0,%1,%2,%3}, {%4,%5,%6,%7}, {%8,%9}, {%0,%1,%2,%3};"
        : "+f"(d[0]), "+f"(d[1]), "+f"(d[2]), "+f"(d[3])
        : "r"(a[0]), "r"(a[1]), "r"(a[2]), "r"(a[3]), "r"(b0), "r"(b1));
}

__device__ __forceinline__ void mma_f16(float (&d)[4], const uint32_t (&a)[4],
                                        uint32_t b0, uint32_t b1) {
    asm volatile(
        "mma.sync.aligned.m16n8k16.row.col.f32.f16.f16.f32 "
        "{%0,%1,%2,%3}, {%4,%5,%6,%7}, {%8,%9}, {%0,%1,%2,%3};"
        : "+f"(d[0]), "+f"(d[1]), "+f"(d[2]), "+f"(d[3])
        : "r"(a[0]), "r"(a[1]), "r"(a[2]), "r"(a[3]), "r"(b0), "r"(b1));
}

__device__ __forceinline__ void cp16(uint32_t dst, const void* src, bool v) {
    int sz = v ? 16 : 0;
    asm volatile("cp.async.cg.shared.global [%0], [%1], 16, %2;\n"
                 :: "r"(dst), "l"(src), "r"(sz) : "memory");
}
__device__ __forceinline__ void cp_commit() {
    asm volatile("cp.async.commit_group;" ::: "memory");
}
template <int n>
__device__ __forceinline__ void cp_wait() {
    asm volatile("cp.async.wait_group %0;" :: "n"(n) : "memory");
}

// ---------------- split fp32 -> bf16 hi/lo planes ----------------
__global__ void split_kernel(const float4* __restrict__ src,
                             uint32_t* __restrict__ hi, uint32_t* __restrict__ lo,
                             int nq) {
    int i = blockIdx.x * 256 + threadIdx.x;
    if (i >= nq) return;
    float4 v = src[i];
    uint32_t h0, l0, h1, l1;
    split2(v.x, v.y, h0, l0);
    split2(v.z, v.w, h1, l1);
    hi[i * 2]     = h0; hi[i * 2 + 1] = h1;
    lo[i * 2]     = l0; lo[i * 2 + 1] = l1;
}

// ---------------- CSR build ----------------
__global__ void build_csr_kernel(const float* __restrict__ adj) {
    int row  = blockIdx.x * (blockDim.x >> 5) + (threadIdx.x >> 5);
    int lane = threadIdx.x & 31;
    if (row >= NN) return;
    const float* arow = adj + (size_t)row * NN;
    int cnt = 0;
    for (int c0 = 0; c0 < NN; c0 += 128) {
        float4 v = *(const float4*)(arow + c0 + lane * 4);
        unsigned m = (v.x != 0.f ? 1u : 0u) | (v.y != 0.f ? 2u : 0u)
                   | (v.z != 0.f ? 4u : 0u) | (v.w != 0.f ? 8u : 0u);
        int c = __popc(m);
        int s = c;
        #pragma unroll
        for (int d = 1; d < 32; d <<= 1) {
            int t = __shfl_up_sync(0xffffffffu, s, d);
            if (lane >= d) s += t;
        }
        int pos = cnt + s - c;
        int base = c0 + lane * 4;
        float vv[4] = {v.x, v.y, v.z, v.w};
        #pragma unroll
        for (int e = 0; e < 4; e++) {
            if ((m >> e) & 1u) {
                if (pos < CAP) {
                    g_cols[row * CAP + pos] = base + e;
                    g_vals[row * CAP + pos] = vv[e];
                }
                pos++;
            }
        }
        cnt += __shfl_sync(0xffffffffu, s, 31);
    }
    if (lane == 0) g_cnt[row] = (cnt < CAP) ? cnt : CAP;
}

// ---------------- SpMM ----------------
// MODE 0: out_f32 = acc; planes + fp16 plane    MODE 1: relu/sigmoid; planes
template <int MODE>
__global__ void __launch_bounds__(256) spmm_kernel(
    const float* __restrict__ X, int ncols,
    float* __restrict__ out_f32,
    __nv_bfloat16* __restrict__ hi, __nv_bfloat16* __restrict__ lo,
    __half* __restrict__ f16out)
{
    int row = blockIdx.x;
    int col = blockIdx.y * 256 + threadIdx.x;
    if (col >= ncols) return;
    int cnt = g_cnt[row];
    const int*   cols = g_cols + row * CAP;
    const float* vals = g_vals + row * CAP;

    float a0 = 0.f, a1 = 0.f, a2 = 0.f, a3 = 0.f;
    int j = 0;
    for (; j + 4 <= cnt; j += 4) {
        int   c0 = cols[j+0], c1 = cols[j+1], c2 = cols[j+2], c3 = cols[j+3];
        float v0 = vals[j+0], v1 = vals[j+1], v2 = vals[j+2], v3 = vals[j+3];
        a0 += v0 * X[(size_t)c0 * ncols + col];
        a1 += v1 * X[(size_t)c1 * ncols + col];
        a2 += v2 * X[(size_t)c2 * ncols + col];
        a3 += v3 * X[(size_t)c3 * ncols + col];
    }
    for (; j < cnt; j++)
        a0 += vals[j] * X[(size_t)cols[j] * ncols + col];
    float acc = (a0 + a1) + (a2 + a3);

    size_t o = (size_t)row * ncols + col;
    float r = (MODE == 1) ? (acc > 0.f ? acc : 0.f) : acc;
    __nv_bfloat16 h = __float2bfloat16_rn(r);
    hi[o] = h;
    lo[o] = __float2bfloat16_rn(r - __bfloat162float(h));
    if (MODE == 0) {
        f16out[o] = __float2half_rn(r);
        out_f32[o] = acc;
    } else {
        out_f32[o] = 1.0f / (1.0f + __expf(-r));
    }
}

// ---------------- bf16x3 mma.sync GEMM, pipelined ----------------
#define GBM 128
#define GBN 128
#define GBK 32
#define STG_BYTES 32768
#define NSTAGE 3
#define SMEM_BYTES (NSTAGE * STG_BYTES)
#define PL_AH 0
#define PL_AL 8192
#define PL_BH 16384
#define PL_BL 24576

__device__ __forceinline__ uint32_t sw_off(int r, int kc) {
    return (uint32_t)(r * 64 + ((kc ^ ((r >> 1) & 3)) << 4));
}

template <int EPI>
__global__ void __launch_bounds__(128, 2) gemm3(
    const __nv_bfloat16* __restrict__ Ah, const __nv_bfloat16* __restrict__ Al,
    const __nv_bfloat16* __restrict__ Bh, const __nv_bfloat16* __restrict__ Bl,
    const float* __restrict__ bias, float* __restrict__ C,
    __nv_bfloat16* __restrict__ Ch, __nv_bfloat16* __restrict__ Cl,
    __half* __restrict__ Cf,
    int M, int N, int K, int ldc)
{
    extern __shared__ uint8_t smem[];
    const uint32_t sbase = (uint32_t)__cvta_generic_to_shared(smem);

    const int tid  = threadIdx.x;
    const int lane = tid & 31;
    const int wid  = tid >> 5;
    const int wm   = wid & 1;
    const int wn   = wid >> 1;
    const int m0   = blockIdx.y * GBM;
    const int n0   = blockIdx.x * GBN;

    float acc[4][8][4];
    #pragma unroll
    for (int i = 0; i < 4; i++)
        #pragma unroll
        for (int j = 0; j < 8; j++)
            #pragma unroll
            for (int q = 0; q < 4; q++) acc[i][j][q] = 0.f;

    auto load_tile = [&](int it, int s) {
        int k0 = it * GBK;
        uint32_t st = sbase + s * STG_BYTES;
        #pragma unroll
        for (int i = 0; i < 4; i++) {
            int f = tid + i * 128;
            int r = f >> 2, c = f & 3;
            uint32_t doff = sw_off(r, c);
            size_t aoff = (size_t)(m0 + r) * K + k0 + c * 8;
            cp16(st + PL_AH + doff, Ah + aoff, true);
            cp16(st + PL_AL + doff, Al + aoff, true);
            bool bv = (n0 + r) < N;
            int  br = bv ? (n0 + r) : 0;
            size_t boff = (size_t)br * K + k0 + c * 8;
            cp16(st + PL_BH + doff, Bh + boff, bv);
            cp16(st + PL_BL + doff, Bl + boff, bv);
        }
        cp_commit();
    };

    auto ldA = [&](uint32_t st, int ks, uint32_t (&ah)[4][4], uint32_t (&al)[4][4]) {
        #pragma unroll
        for (int mt = 0; mt < 4; mt++) {
            int rr = wm * 64 + mt * 16 + ((lane >> 3) & 1) * 8 + (lane & 7);
            int kc = ks * 2 + (lane >> 4);
            uint32_t off = sw_off(rr, kc);
            ldsm4(ah[mt][0], ah[mt][1], ah[mt][2], ah[mt][3], st + PL_AH + off);
            ldsm4(al[mt][0], al[mt][1], al[mt][2], al[mt][3], st + PL_AL + off);
        }
    };
    auto ldB = [&](uint32_t st, int ks, int g, uint32_t (&bh)[4], uint32_t (&bl)[4]) {
        int rr = wn * 64 + g * 16 + (lane >> 4) * 8 + (lane & 7);
        int kc = ks * 2 + ((lane >> 3) & 1);
        uint32_t off = sw_off(rr, kc);
        ldsm4(bh[0], bh[1], bh[2], bh[3], st + PL_BH + off);
        ldsm4(bl[0], bl[1], bl[2], bl[3], st + PL_BL + off);
    };
    auto mma_group = [&](int g, uint32_t (&ah)[4][4], uint32_t (&al)[4][4],
                         uint32_t (&bh)[4], uint32_t (&bl)[4]) {
        #pragma unroll
        for (int h = 0; h < 2; h++) {
            int nt = g * 2 + h;
            #pragma unroll
            for (int mt = 0; mt < 4; mt++) {
                mma_bf16(acc[mt][nt], ah[mt], bh[h * 2], bh[h * 2 + 1]);
                mma_bf16(acc[mt][nt], al[mt], bh[h * 2], bh[h * 2 + 1]);
                mma_bf16(acc[mt][nt], ah[mt], bl[h * 2], bl[h * 2 + 1]);
            }
        }
    };

    const int nIt = K / GBK;
    load_tile(0, 0);
    if (nIt > 1) load_tile(1, 1);

    for (int it = 0; it < nIt; it++) {
        if (it + 1 < nIt) cp_wait<1>(); else cp_wait<0>();
        __syncthreads();
        if (it + 2 < nIt) load_tile(it + 2, (it + 2) % NSTAGE);

        uint32_t st = sbase + (it % NSTAGE) * STG_BYTES;

        uint32_t ah0[4][4], al0[4][4], ah1[4][4], al1[4][4];
        uint32_t bhA[4], blA[4], bhB[4], blB[4];

        ldA(st, 0, ah0, al0);
        ldB(st, 0, 0, bhA, blA);
        ldB(st, 0, 1, bhB, blB);
        mma_group(0, ah0, al0, bhA, blA);
        ldB(st, 0, 2, bhA, blA);
        mma_group(1, ah0, al0, bhB, blB);
        ldB(st, 0, 3, bhB, blB);
        mma_group(2, ah0, al0, bhA, blA);
        ldA(st, 1, ah1, al1);
        mma_group(3, ah0, al0, bhB, blB);

        ldB(st, 1, 0, bhA, blA);
        ldB(st, 1, 1, bhB, blB);
        mma_group(0, ah1, al1, bhA, blA);
        ldB(st, 1, 2, bhA, blA);
        mma_group(1, ah1, al1, bhB, blB);
        ldB(st, 1, 3, bhB, blB);
        mma_group(2, ah1, al1, bhA, blA);
        mma_group(3, ah1, al1, bhB, blB);

        __syncthreads();
    }

    #pragma unroll
    for (int mt = 0; mt < 4; mt++) {
        int row = m0 + wm * 64 + mt * 16 + (lane >> 2);
        #pragma unroll
        for (int nt = 0; nt < 8; nt++) {
            int col = n0 + wn * 64 + nt * 8 + (lane & 3) * 2;
            if (col < N) {
                float c0 = acc[mt][nt][0], c1 = acc[mt][nt][1];
                float c2 = acc[mt][nt][2], c3 = acc[mt][nt][3];
                if (EPI == 1) {
                    float b0 = bias[col], b1 = bias[col + 1];
                    c0 += b0; c1 += b1; c2 += b0; c3 += b1;
                    c0 = (c0 >= 0.f) ? c0 : 0.1f * c0;
                    c1 = (c1 >= 0.f) ? c1 : 0.1f * c1;
                    c2 = (c2 >= 0.f) ? c2 : 0.1f * c2;
                    c3 = (c3 >= 0.f) ? c3 : 0.1f * c3;
                    uint32_t h, l;
                    split2(c0, c1, h, l);
                    *(uint32_t*)(Ch + (size_t)row * ldc + col) = h;
                    *(uint32_t*)(Cl + (size_t)row * ldc + col) = l;
                    split2(c2, c3, h, l);
                    *(uint32_t*)(Ch + (size_t)(row + 8) * ldc + col) = h;
                    *(uint32_t*)(Cl + (size_t)(row + 8) * ldc + col) = l;
                    __half2 f0 = __floats2half2_rn(c0, c1);
                    __half2 f1 = __floats2half2_rn(c2, c3);
                    *(__half2*)(Cf + (size_t)row * ldc + col)       = f0;
                    *(__half2*)(Cf + (size_t)(row + 8) * ldc + col) = f1;
                } else {
                    *(float2*)(C + (size_t)row * ldc + col)       = make_float2(c0, c1);
                    *(float2*)(C + (size_t)(row + 8) * ldc + col) = make_float2(c2, c3);
                }
            }
        }
    }
}

// ---------------- fp16 single-pass pred kernel ----------------
// pred[128x128 tile] = zf[m0:, 0:192] @ tzf[n0:, 0:192]^T, fp32 accumulate.
// Whole K panel (A: 48KB, B: 48KB fp16) loaded to smem once; no mainloop syncs.
// A at 0, B at 49152; each = 3 sub-tiles of 128 rows x 64 fp16 (128B swizzled rows).
#define PF_SMEM 98304

__global__ void __launch_bounds__(128, 2) pred_f16(
    const __half* __restrict__ Af, const __half* __restrict__ Bf,
    float* __restrict__ C)
{
    extern __shared__ uint8_t smem[];
    const uint32_t sbase = (uint32_t)__cvta_generic_to_shared(smem);
    const int tid  = threadIdx.x;
    const int lane = tid & 31;
    const int wid  = tid >> 5;
    const int wm   = wid & 1;
    const int wn   = wid >> 1;
    const int m0   = blockIdx.y * 128;
    const int n0   = blockIdx.x * 128;

    // load both panels: 24 chunks/row * 128 rows * 2 panels = 6144 chunks
    #pragma unroll
    for (int i = 0; i < 24; i++) {
        int f = tid + i * 128;           // 0..3071 per panel
        int r = f / 24, c = f % 24;
        int sub = c >> 3, cc = c & 7;
        uint32_t doff = (uint32_t)(sub * 16384 + r * 128 + ((cc ^ (r & 7)) << 4));
        cp16(sbase + doff,         Af + (size_t)(m0 + r) * ZD + c * 8, true);
        cp16(sbase + 49152 + doff, Bf + (size_t)(n0 + r) * ZD + c * 8, true);
    }
    cp_commit();
    cp_wait<0>();
    __syncthreads();

    float acc[4][8][4];
    #pragma unroll
    for (int i = 0; i < 4; i++)
        #pragma unroll
        for (int j = 0; j < 8; j++)
            #pragma unroll
            for (int q = 0; q < 4; q++) acc[i][j][q] = 0.f;

    #pragma unroll
    for (int ks = 0; ks < 12; ks++) {
        int sub = ks >> 2;
        uint32_t sA = sbase + sub * 16384;
        uint32_t sB = sbase + 49152 + sub * 16384;
        uint32_t a[4][4], b[4][4];
        #pragma unroll
        for (int mt = 0; mt < 4; mt++) {
            int rr = wm * 64 + mt * 16 + ((lane >> 3) & 1) * 8 + (lane & 7);
            int kc = (ks & 3) * 2 + (lane >> 4);
            uint32_t off = (uint32_t)(rr * 128 + ((kc ^ (rr & 7)) << 4));
            ldsm4(a[mt][0], a[mt][1], a[mt][2], a[mt][3], sA + off);
        }
        #pragma unroll
        for (int g = 0; g < 4; g++) {
            int rr = wn * 64 + g * 16 + (lane >> 4) * 8 + (lane & 7);
            int kc = (ks & 3) * 2 + ((lane >> 3) & 1);
            uint32_t off = (uint32_t)(rr * 128 + ((kc ^ (rr & 7)) << 4));
            ldsm4(b[g][0], b[g][1], b[g][2], b[g][3], sB + off);
        }
        #pragma unroll
        for (int mt = 0; mt < 4; mt++)
            #pragma unroll
            for (int nt = 0; nt < 8; nt++)
                mma_f16(acc[mt][nt], a[mt],
                        b[nt >> 1][(nt & 1) * 2], b[nt >> 1][(nt & 1) * 2 + 1]);
    }

    #pragma unroll
    for (int mt = 0; mt < 4; mt++) {
        int row = m0 + wm * 64 + mt * 16 + (lane >> 2);
        #pragma unroll
        for (int nt = 0; nt < 8; nt++) {
            int col = n0 + wn * 64 + nt * 8 + (lane & 3) * 2;
            *(float2*)(C + (size_t)row * NN + col) =
                make_float2(acc[mt][nt][0], acc[mt][nt][1]);
            *(float2*)(C + (size_t)(row + 8) * NN + col) =
                make_float2(acc[mt][nt][2], acc[mt][nt][3]);
        }
    }
}

// ---------------- launch ----------------
static inline void* sym_addr(const void* sym) {
    void* p = nullptr;
    cudaGetSymbolAddress(&p, sym);
    return p;
}

extern "C" void kernel_launch(void* const* d_in, const int* in_sizes, int n_in,
                              void* d_out, int out_size)
{
    const float* adj = (const float*)d_in[0];
    const float* x   = (const float*)d_in[1];
    const float* W1  = (const float*)d_in[2];
    const float* W2  = (const float*)d_in[3];
    const float* Wm1 = (const float*)d_in[4];
    const float* Wm2 = (const float*)d_in[5];
    const float* Wm3 = (const float*)d_in[6];
    const float* Wt  = (const float*)d_in[7];
    const float* bt  = (const float*)d_in[8];

    float* out = (float*)d_out;
    float* out_pred = out;
    float* out_x1   = out + (size_t)NN * NN;
    float* out_x2   = out_x1 + (size_t)NN * H1;
    float* out_z    = out_x2 + (size_t)NN * H2;

    float* t1 = (float*)sym_addr(g_t1);
    float* t2 = (float*)sym_addr(g_t2);
    float* tm = (float*)sym_addr(g_tm);
    __nv_bfloat16* xh  = (__nv_bfloat16*)sym_addr(g_xh);
    __nv_bfloat16* xl  = (__nv_bfloat16*)sym_addr(g_xl);
    __nv_bfloat16* x1h = (__nv_bfloat16*)sym_addr(g_x1h);
    __nv_bfloat16* x1l = (__nv_bfloat16*)sym_addr(g_x1l);
    __nv_bfloat16* x2h = (__nv_bfloat16*)sym_addr(g_x2h);
    __nv_bfloat16* x2l = (__nv_bfloat16*)sym_addr(g_x2l);
    __nv_bfloat16* zh  = (__nv_bfloat16*)sym_addr(g_zh);
    __nv_bfloat16* zl  = (__nv_bfloat16*)sym_addr(g_zl);
    __nv_bfloat16* tzh = (__nv_bfloat16*)sym_addr(g_tzh);
    __nv_bfloat16* tzl = (__nv_bfloat16*)sym_addr(g_tzl);
    __half* zf  = (__half*)sym_addr(g_zf);
    __half* tzf = (__half*)sym_addr(g_tzf);
    __nv_bfloat16* W1h = (__nv_bfloat16*)sym_addr(g_W1h);
    __nv_bfloat16* W1l = (__nv_bfloat16*)sym_addr(g_W1l);
    __nv_bfloat16* W2h = (__nv_bfloat16*)sym_addr(g_W2h);
    __nv_bfloat16* W2l = (__nv_bfloat16*)sym_addr(g_W2l);
    __nv_bfloat16* Wmh = (__nv_bfloat16*)sym_addr(g_Wmh);
    __nv_bfloat16* Wml = (__nv_bfloat16*)sym_addr(g_Wml);
    __nv_bfloat16* Wth = (__nv_bfloat16*)sym_addr(g_Wth);
    __nv_bfloat16* Wtl = (__nv_bfloat16*)sym_addr(g_Wtl);

    cudaFuncSetAttribute((const void*)gemm3<0>,
                         cudaFuncAttributeMaxDynamicSharedMemorySize, SMEM_BYTES);
    cudaFuncSetAttribute((const void*)gemm3<1>,
                         cudaFuncAttributeMaxDynamicSharedMemorySize, SMEM_BYTES);
    cudaFuncSetAttribute((const void*)pred_f16,
                         cudaFuncAttributeMaxDynamicSharedMemorySize, PF_SMEM);

    auto launch_split = [&](const float* src, __nv_bfloat16* h, __nv_bfloat16* l, int n) {
        int nq = n / 4;
        split_kernel<<<(nq + 255) / 256, 256>>>((const float4*)src,
                                                (uint32_t*)h, (uint32_t*)l, nq);
    };
    launch_split(x,   xh,  xl,  NN * IN_DIM);
    launch_split(W1,  W1h, W1l, H1 * IN_DIM);
    launch_split(W2,  W2h, W2l, H2 * H1);
    launch_split(Wm1, Wmh,            Wml,            64 * H2);
    launch_split(Wm2, Wmh + 64 * H2,  Wml + 64 * H2,  64 * H2);
    launch_split(Wm3, Wmh + 128 * H2, Wml + 128 * H2, 64 * H2);
    launch_split(Wt,  Wth, Wtl, ZD * ZD);

    build_csr_kernel<<<NN / 8, 256>>>(adj);

    // t1 = x @ W1^T
    gemm3<0><<<dim3(H1 / GBN, NN / GBM), 128, SMEM_BYTES>>>(
        xh, xl, W1h, W1l, nullptr, t1, nullptr, nullptr, nullptr, NN, H1, IN_DIM, H1);
    // x1 planes + sigmoid
    spmm_kernel<1><<<dim3(NN, H1 / 256), 256>>>(t1, H1, out_x1, x1h, x1l, nullptr);
    // t2 = x1 @ W2^T
    gemm3<0><<<dim3(H2 / GBN, NN / GBM), 128, SMEM_BYTES>>>(
        x1h, x1l, W2h, W2l, nullptr, t2, nullptr, nullptr, nullptr, NN, H2, H1, H2);
    // x2 planes + sigmoid
    spmm_kernel<1><<<dim3(NN, 1), 256>>>(t2, H2, out_x2, x2h, x2l, nullptr);
    // tm = x2 @ Wm^T
    gemm3<0><<<dim3(2, NN / GBM), 128, SMEM_BYTES>>>(
        x2h, x2l, Wmh, Wml, nullptr, tm, nullptr, nullptr, nullptr, NN, ZD, H2, ZD);
    // z = adj @ tm  -> fp32 + bf16 planes + fp16 plane
    spmm_kernel<0><<<dim3(NN, 1), 256>>>(tm, ZD, out_z, zh, zl, zf);
    // tz = leaky(z @ Wt^T + bt) -> bf16 planes + fp16 plane
    gemm3<1><<<dim3(2, NN / GBM), 128, SMEM_BYTES>>>(
        zh, zl, Wth, Wtl, bt, nullptr, tzh, tzl, tzf, NN, ZD, ZD, ZD);
    // pred = zf @ tzf^T  (fp16 single pass)
    pred_f16<<<dim3(NN / 128, NN / 128), 128, PF_SMEM>>>(zf, tzf, out_pred);

    (void)in_sizes; (void)n_in; (void)out_size;
}

// round 10
// speedup vs baseline: 3.8191x; 1.1899x over previous
#include <cuda_runtime.h>
#include <cuda_bf16.h>
#include <cuda_fp16.h>
#include <math.h>
#include <stdint.h>

// Problem dims
#define NN      8192
#define IN_DIM  1024
#define H1      512
#define H2      256
#define ZD      192
#define CAP     192

// ---------------- device scratch ----------------
__device__ float g_t1[NN * H1];
__device__ float g_t2[NN * H2];
__device__ float g_tm[NN * ZD];
__device__ __nv_bfloat16 g_xh [NN * IN_DIM];
__device__ __nv_bfloat16 g_xl [NN * IN_DIM];
__device__ __nv_bfloat16 g_x1h[NN * H1];
__device__ __nv_bfloat16 g_x1l[NN * H1];
__device__ __nv_bfloat16 g_x2h[NN * H2];
__device__ __nv_bfloat16 g_x2l[NN * H2];
__device__ __nv_bfloat16 g_zh [NN * ZD];
__device__ __nv_bfloat16 g_zl [NN * ZD];
__device__ __half        g_zf [NN * ZD];
__device__ __half        g_tzf[NN * ZD];
__device__ __nv_bfloat16 g_W1h[H1 * IN_DIM];
__device__ __nv_bfloat16 g_W1l[H1 * IN_DIM];
__device__ __nv_bfloat16 g_W2h[H2 * H1];
__device__ __nv_bfloat16 g_W2l[H2 * H1];
__device__ __nv_bfloat16 g_Wmh[ZD * H2];
__device__ __nv_bfloat16 g_Wml[ZD * H2];
__device__ __nv_bfloat16 g_Wth[ZD * ZD];
__device__ __nv_bfloat16 g_Wtl[ZD * ZD];
__device__ float g_vals[NN * CAP];
__device__ int   g_cols[NN * CAP];
__device__ int   g_cnt [NN];

// ---------------- helpers ----------------
__device__ __forceinline__ void split2(float v0, float v1, uint32_t& hi, uint32_t& lo) {
    __nv_bfloat16 h0 = __float2bfloat16_rn(v0);
    __nv_bfloat16 h1 = __float2bfloat16_rn(v1);
    __nv_bfloat16 l0 = __float2bfloat16_rn(v0 - __bfloat162float(h0));
    __nv_bfloat16 l1 = __float2bfloat16_rn(v1 - __bfloat162float(h1));
    hi = (uint32_t)__bfloat16_as_ushort(h0) | ((uint32_t)__bfloat16_as_ushort(h1) << 16);
    lo = (uint32_t)__bfloat16_as_ushort(l0) | ((uint32_t)__bfloat16_as_ushort(l1) << 16);
}

__device__ __forceinline__ uint32_t h2_as_u32(__half2 h) {
    uint32_t u;
    memcpy(&u, &h, 4);
    return u;
}

__device__ __forceinline__ void ldsm4(uint32_t& r0, uint32_t& r1, uint32_t& r2,
                                      uint32_t& r3, uint32_t addr) {
    asm volatile("ldmatrix.sync.aligned.m8n8.x4.shared.b16 {%0,%1,%2,%3}, [%4];"
                 : "=r"(r0), "=r"(r1), "=r"(r2), "=r"(r3) : "r"(addr));
}

__device__ __forceinline__ void mma_bf16(float (&d)[4], const uint32_t (&a)[4],
                                         uint32_t b0, uint32_t b1) {
    asm volatile(
        "mma.sync.aligned.m16n8k16.row.col.f32.bf16.bf16.f32 "
        "{%0,%1,%2,%3}, {%4,%5,%6,%7}, {%8,%9}, {%0,%1,%2,%3};"
        : "+f"(d[0]), "+f"(d[1]), "+f"(d[2]), "+f"(d[3])
        : "r"(a[0]), "r"(a[1]), "r"(a[2]), "r"(a[3]), "r"(b0), "r"(b1));
}

__device__ __forceinline__ void mma_f16(float (&d)[4], const uint32_t (&a)[4],
                                        uint32_t b0, uint32_t b1) {
    asm volatile(
        "mma.sync.aligned.m16n8k16.row.col.f32.f16.f16.f32 "
        "{%0,%1,%2,%3}, {%4,%5,%6,%7}, {%8,%9}, {%0,%1,%2,%3};"
        : "+f"(d[0]), "+f"(d[1]), "+f"(d[2]), "+f"(d[3])
        : "r"(a[0]), "r"(a[1]), "r"(a[2]), "r"(a[3]), "r"(b0), "r"(b1));
}

__device__ __forceinline__ void cp16(uint32_t dst, const void* src, bool v) {
    int sz = v ? 16 : 0;
    asm volatile("cp.async.cg.shared.global [%0], [%1], 16, %2;\n"
                 :: "r"(dst), "l"(src), "r"(sz) : "memory");
}
__device__ __forceinline__ void cp_commit() {
    asm volatile("cp.async.commit_group;" ::: "memory");
}
template <int n>
__device__ __forceinline__ void cp_wait() {
    asm volatile("cp.async.wait_group %0;" :: "n"(n) : "memory");
}

// ---------------- merged split: fp32 -> bf16 hi/lo planes, 7 segments ----------------
#define NSEG 7
struct SplitArgs {
    const float4* src[NSEG];
    uint32_t*     hi [NSEG];
    uint32_t*     lo [NSEG];
    int blk_off[NSEG + 1];
    int nq[NSEG];
};

__global__ void __launch_bounds__(256) split_all_kernel(SplitArgs a) {
    int b = blockIdx.x;
    int s = 0;
    #pragma unroll
    for (int k = 1; k < NSEG; k++)
        if (b >= a.blk_off[k]) s = k;
    int i = (b - a.blk_off[s]) * 256 + threadIdx.x;
    if (i >= a.nq[s]) return;
    float4 v = a.src[s][i];
    uint32_t h0, l0, h1, l1;
    split2(v.x, v.y, h0, l0);
    split2(v.z, v.w, h1, l1);
    a.hi[s][i * 2]     = h0; a.hi[s][i * 2 + 1] = h1;
    a.lo[s][i * 2]     = l0; a.lo[s][i * 2 + 1] = l1;
}

// ---------------- CSR build ----------------
__global__ void build_csr_kernel(const float* __restrict__ adj) {
    int row  = blockIdx.x * (blockDim.x >> 5) + (threadIdx.x >> 5);
    int lane = threadIdx.x & 31;
    if (row >= NN) return;
    const float* arow = adj + (size_t)row * NN;
    int cnt = 0;
    for (int c0 = 0; c0 < NN; c0 += 128) {
        float4 v = *(const float4*)(arow + c0 + lane * 4);
        unsigned m = (v.x != 0.f ? 1u : 0u) | (v.y != 0.f ? 2u : 0u)
                   | (v.z != 0.f ? 4u : 0u) | (v.w != 0.f ? 8u : 0u);
        int c = __popc(m);
        int s = c;
        #pragma unroll
        for (int d = 1; d < 32; d <<= 1) {
            int t = __shfl_up_sync(0xffffffffu, s, d);
            if (lane >= d) s += t;
        }
        int pos = cnt + s - c;
        int base = c0 + lane * 4;
        float vv[4] = {v.x, v.y, v.z, v.w};
        #pragma unroll
        for (int e = 0; e < 4; e++) {
            if ((m >> e) & 1u) {
                if (pos < CAP) {
                    g_cols[row * CAP + pos] = base + e;
                    g_vals[row * CAP + pos] = vv[e];
                }
                pos++;
            }
        }
        cnt += __shfl_sync(0xffffffffu, s, 31);
    }
    if (lane == 0) g_cnt[row] = (cnt < CAP) ? cnt : CAP;
}

// ---------------- SpMM, float4-vectorized ----------------
// Each thread owns 4 consecutive columns of one row. ncq = ncols/4.
// MODE 0: out_f32 = acc; hi/lo planes; fp16 plane.
// MODE 1: hi/lo = split(relu(acc)); out_f32 = sigmoid(relu(acc)).
template <int MODE>
__global__ void spmm4_kernel(
    const float4* __restrict__ X, int ncq, int rpc,
    float4* __restrict__ out_f32,
    uint2* __restrict__ hi, uint2* __restrict__ lo,
    uint2* __restrict__ f16out)
{
    int t = threadIdx.x;
    int r = t / ncq;
    int c = t - r * ncq;
    int row = blockIdx.x * rpc + r;
    if (r >= rpc || row >= NN) return;

    int cnt = g_cnt[row];
    const int*   cols = g_cols + row * CAP;
    const float* vals = g_vals + row * CAP;

    float4 a0 = {0,0,0,0}, a1 = {0,0,0,0}, a2 = {0,0,0,0}, a3 = {0,0,0,0};
    int j = 0;
    for (; j + 4 <= cnt; j += 4) {
        int   c0 = cols[j+0], c1 = cols[j+1], c2 = cols[j+2], c3 = cols[j+3];
        float v0 = vals[j+0], v1 = vals[j+1], v2 = vals[j+2], v3 = vals[j+3];
        float4 x0 = X[(size_t)c0 * ncq + c];
        float4 x1 = X[(size_t)c1 * ncq + c];
        float4 x2 = X[(size_t)c2 * ncq + c];
        float4 x3 = X[(size_t)c3 * ncq + c];
        a0.x += v0 * x0.x; a0.y += v0 * x0.y; a0.z += v0 * x0.z; a0.w += v0 * x0.w;
        a1.x += v1 * x1.x; a1.y += v1 * x1.y; a1.z += v1 * x1.z; a1.w += v1 * x1.w;
        a2.x += v2 * x2.x; a2.y += v2 * x2.y; a2.z += v2 * x2.z; a2.w += v2 * x2.w;
        a3.x += v3 * x3.x; a3.y += v3 * x3.y; a3.z += v3 * x3.z; a3.w += v3 * x3.w;
    }
    for (; j < cnt; j++) {
        float v = vals[j];
        float4 xv = X[(size_t)cols[j] * ncq + c];
        a0.x += v * xv.x; a0.y += v * xv.y; a0.z += v * xv.z; a0.w += v * xv.w;
    }
    float4 acc;
    acc.x = (a0.x + a1.x) + (a2.x + a3.x);
    acc.y = (a0.y + a1.y) + (a2.y + a3.y);
    acc.z = (a0.z + a1.z) + (a2.z + a3.z);
    acc.w = (a0.w + a1.w) + (a2.w + a3.w);

    size_t o = (size_t)row * ncq + c;
    float4 rr;
    if (MODE == 1) {
        rr.x = acc.x > 0.f ? acc.x : 0.f;
        rr.y = acc.y > 0.f ? acc.y : 0.f;
        rr.z = acc.z > 0.f ? acc.z : 0.f;
        rr.w = acc.w > 0.f ? acc.w : 0.f;
    } else {
        rr = acc;
    }
    uint2 h, l;
    split2(rr.x, rr.y, h.x, l.x);
    split2(rr.z, rr.w, h.y, l.y);
    hi[o] = h;
    lo[o] = l;
    if (MODE == 0) {
        uint2 f;
        f.x = h2_as_u32(__floats2half2_rn(rr.x, rr.y));
        f.y = h2_as_u32(__floats2half2_rn(rr.z, rr.w));
        f16out[o] = f;
        out_f32[o] = acc;
    } else {
        float4 s;
        s.x = 1.0f / (1.0f + __expf(-rr.x));
        s.y = 1.0f / (1.0f + __expf(-rr.y));
        s.z = 1.0f / (1.0f + __expf(-rr.z));
        s.w = 1.0f / (1.0f + __expf(-rr.w));
        out_f32[o] = s;
    }
}

// ---------------- bf16x3 mma.sync GEMM, pipelined ----------------
#define GBM 128
#define GBN 128
#define GBK 32
#define STG_BYTES 32768
#define NSTAGE 3
#define SMEM_BYTES (NSTAGE * STG_BYTES)
#define PL_AH 0
#define PL_AL 8192
#define PL_BH 16384
#define PL_BL 24576

__device__ __forceinline__ uint32_t sw_off(int r, int kc) {
    return (uint32_t)(r * 64 + ((kc ^ ((r >> 1) & 3)) << 4));
}

// EPI 0: fp32 store. EPI 1: +bias, leaky_relu(0.1) -> fp16 plane only.
template <int EPI>
__global__ void __launch_bounds__(128, 2) gemm3(
    const __nv_bfloat16* __restrict__ Ah, const __nv_bfloat16* __restrict__ Al,
    const __nv_bfloat16* __restrict__ Bh, const __nv_bfloat16* __restrict__ Bl,
    const float* __restrict__ bias, float* __restrict__ C,
    __half* __restrict__ Cf,
    int M, int N, int K, int ldc)
{
    extern __shared__ uint8_t smem[];
    const uint32_t sbase = (uint32_t)__cvta_generic_to_shared(smem);

    const int tid  = threadIdx.x;
    const int lane = tid & 31;
    const int wid  = tid >> 5;
    const int wm   = wid & 1;
    const int wn   = wid >> 1;
    const int m0   = blockIdx.y * GBM;
    const int n0   = blockIdx.x * GBN;

    float acc[4][8][4];
    #pragma unroll
    for (int i = 0; i < 4; i++)
        #pragma unroll
        for (int j = 0; j < 8; j++)
            #pragma unroll
            for (int q = 0; q < 4; q++) acc[i][j][q] = 0.f;

    auto load_tile = [&](int it, int s) {
        int k0 = it * GBK;
        uint32_t st = sbase + s * STG_BYTES;
        #pragma unroll
        for (int i = 0; i < 4; i++) {
            int f = tid + i * 128;
            int r = f >> 2, c = f & 3;
            uint32_t doff = sw_off(r, c);
            size_t aoff = (size_t)(m0 + r) * K + k0 + c * 8;
            cp16(st + PL_AH + doff, Ah + aoff, true);
            cp16(st + PL_AL + doff, Al + aoff, true);
            bool bv = (n0 + r) < N;
            int  br = bv ? (n0 + r) : 0;
            size_t boff = (size_t)br * K + k0 + c * 8;
            cp16(st + PL_BH + doff, Bh + boff, bv);
            cp16(st + PL_BL + doff, Bl + boff, bv);
        }
        cp_commit();
    };

    auto ldA = [&](uint32_t st, int ks, uint32_t (&ah)[4][4], uint32_t (&al)[4][4]) {
        #pragma unroll
        for (int mt = 0; mt < 4; mt++) {
            int rr = wm * 64 + mt * 16 + ((lane >> 3) & 1) * 8 + (lane & 7);
            int kc = ks * 2 + (lane >> 4);
            uint32_t off = sw_off(rr, kc);
            ldsm4(ah[mt][0], ah[mt][1], ah[mt][2], ah[mt][3], st + PL_AH + off);
            ldsm4(al[mt][0], al[mt][1], al[mt][2], al[mt][3], st + PL_AL + off);
        }
    };
    auto ldB = [&](uint32_t st, int ks, int g, uint32_t (&bh)[4], uint32_t (&bl)[4]) {
        int rr = wn * 64 + g * 16 + (lane >> 4) * 8 + (lane & 7);
        int kc = ks * 2 + ((lane >> 3) & 1);
        uint32_t off = sw_off(rr, kc);
        ldsm4(bh[0], bh[1], bh[2], bh[3], st + PL_BH + off);
        ldsm4(bl[0], bl[1], bl[2], bl[3], st + PL_BL + off);
    };
    auto mma_group = [&](int g, uint32_t (&ah)[4][4], uint32_t (&al)[4][4],
                         uint32_t (&bh)[4], uint32_t (&bl)[4]) {
        #pragma unroll
        for (int h = 0; h < 2; h++) {
            int nt = g * 2 + h;
            #pragma unroll
            for (int mt = 0; mt < 4; mt++) {
                mma_bf16(acc[mt][nt], ah[mt], bh[h * 2], bh[h * 2 + 1]);
                mma_bf16(acc[mt][nt], al[mt], bh[h * 2], bh[h * 2 + 1]);
                mma_bf16(acc[mt][nt], ah[mt], bl[h * 2], bl[h * 2 + 1]);
            }
        }
    };

    const int nIt = K / GBK;
    load_tile(0, 0);
    if (nIt > 1) load_tile(1, 1);

    for (int it = 0; it < nIt; it++) {
        if (it + 1 < nIt) cp_wait<1>(); else cp_wait<0>();
        __syncthreads();
        if (it + 2 < nIt) load_tile(it + 2, (it + 2) % NSTAGE);

        uint32_t st = sbase + (it % NSTAGE) * STG_BYTES;

        uint32_t ah0[4][4], al0[4][4], ah1[4][4], al1[4][4];
        uint32_t bhA[4], blA[4], bhB[4], blB[4];

        ldA(st, 0, ah0, al0);
        ldB(st, 0, 0, bhA, blA);
        ldB(st, 0, 1, bhB, blB);
        mma_group(0, ah0, al0, bhA, blA);
        ldB(st, 0, 2, bhA, blA);
        mma_group(1, ah0, al0, bhB, blB);
        ldB(st, 0, 3, bhB, blB);
        mma_group(2, ah0, al0, bhA, blA);
        ldA(st, 1, ah1, al1);
        mma_group(3, ah0, al0, bhB, blB);

        ldB(st, 1, 0, bhA, blA);
        ldB(st, 1, 1, bhB, blB);
        mma_group(0, ah1, al1, bhA, blA);
        ldB(st, 1, 2, bhA, blA);
        mma_group(1, ah1, al1, bhB, blB);
        ldB(st, 1, 3, bhB, blB);
        mma_group(2, ah1, al1, bhA, blA);
        mma_group(3, ah1, al1, bhB, blB);

        __syncthreads();
    }

    #pragma unroll
    for (int mt = 0; mt < 4; mt++) {
        int row = m0 + wm * 64 + mt * 16 + (lane >> 2);
        #pragma unroll
        for (int nt = 0; nt < 8; nt++) {
            int col = n0 + wn * 64 + nt * 8 + (lane & 3) * 2;
            if (col < N) {
                float c0 = acc[mt][nt][0], c1 = acc[mt][nt][1];
                float c2 = acc[mt][nt][2], c3 = acc[mt][nt][3];
                if (EPI == 1) {
                    float b0 = bias[col], b1 = bias[col + 1];
                    c0 += b0; c1 += b1; c2 += b0; c3 += b1;
                    c0 = (c0 >= 0.f) ? c0 : 0.1f * c0;
                    c1 = (c1 >= 0.f) ? c1 : 0.1f * c1;
                    c2 = (c2 >= 0.f) ? c2 : 0.1f * c2;
                    c3 = (c3 >= 0.f) ? c3 : 0.1f * c3;
                    *(__half2*)(Cf + (size_t)row * ldc + col)       = __floats2half2_rn(c0, c1);
                    *(__half2*)(Cf + (size_t)(row + 8) * ldc + col) = __floats2half2_rn(c2, c3);
                } else {
                    *(float2*)(C + (size_t)row * ldc + col)       = make_float2(c0, c1);
                    *(float2*)(C + (size_t)(row + 8) * ldc + col) = make_float2(c2, c3);
                }
            }
        }
    }
}

// ---------------- fp16 single-pass pred kernel ----------------
#define PF_SMEM 98304

__global__ void __launch_bounds__(128, 2) pred_f16(
    const __half* __restrict__ Af, const __half* __restrict__ Bf,
    float* __restrict__ C)
{
    extern __shared__ uint8_t smem[];
    const uint32_t sbase = (uint32_t)__cvta_generic_to_shared(smem);
    const int tid  = threadIdx.x;
    const int lane = tid & 31;
    const int wid  = tid >> 5;
    const int wm   = wid & 1;
    const int wn   = wid >> 1;
    const int m0   = blockIdx.y * 128;
    const int n0   = blockIdx.x * 128;

    #pragma unroll
    for (int i = 0; i < 24; i++) {
        int f = tid + i * 128;
        int r = f / 24, c = f % 24;
        int sub = c >> 3, cc = c & 7;
        uint32_t doff = (uint32_t)(sub * 16384 + r * 128 + ((cc ^ (r & 7)) << 4));
        cp16(sbase + doff,         Af + (size_t)(m0 + r) * ZD + c * 8, true);
        cp16(sbase + 49152 + doff, Bf + (size_t)(n0 + r) * ZD + c * 8, true);
    }
    cp_commit();
    cp_wait<0>();
    __syncthreads();

    float acc[4][8][4];
    #pragma unroll
    for (int i = 0; i < 4; i++)
        #pragma unroll
        for (int j = 0; j < 8; j++)
            #pragma unroll
            for (int q = 0; q < 4; q++) acc[i][j][q] = 0.f;

    #pragma unroll
    for (int ks = 0; ks < 12; ks++) {
        int sub = ks >> 2;
        uint32_t sA = sbase + sub * 16384;
        uint32_t sB = sbase + 49152 + sub * 16384;
        uint32_t a[4][4], b[4][4];
        #pragma unroll
        for (int mt = 0; mt < 4; mt++) {
            int rr = wm * 64 + mt * 16 + ((lane >> 3) & 1) * 8 + (lane & 7);
            int kc = (ks & 3) * 2 + (lane >> 4);
            uint32_t off = (uint32_t)(rr * 128 + ((kc ^ (rr & 7)) << 4));
            ldsm4(a[mt][0], a[mt][1], a[mt][2], a[mt][3], sA + off);
        }
        #pragma unroll
        for (int g = 0; g < 4; g++) {
            int rr = wn * 64 + g * 16 + (lane >> 4) * 8 + (lane & 7);
            int kc = (ks & 3) * 2 + ((lane >> 3) & 1);
            uint32_t off = (uint32_t)(rr * 128 + ((kc ^ (rr & 7)) << 4));
            ldsm4(b[g][0], b[g][1], b[g][2], b[g][3], sB + off);
        }
        #pragma unroll
        for (int mt = 0; mt < 4; mt++)
            #pragma unroll
            for (int nt = 0; nt < 8; nt++)
                mma_f16(acc[mt][nt], a[mt],
                        b[nt >> 1][(nt & 1) * 2], b[nt >> 1][(nt & 1) * 2 + 1]);
    }

    #pragma unroll
    for (int mt = 0; mt < 4; mt++) {
        int row = m0 + wm * 64 + mt * 16 + (lane >> 2);
        #pragma unroll
        for (int nt = 0; nt < 8; nt++) {
            int col = n0 + wn * 64 + nt * 8 + (lane & 3) * 2;
            *(float2*)(C + (size_t)row * NN + col) =
                make_float2(acc[mt][nt][0], acc[mt][nt][1]);
            *(float2*)(C + (size_t)(row + 8) * NN + col) =
                make_float2(acc[mt][nt][2], acc[mt][nt][3]);
        }
    }
}

// ---------------- launch ----------------
static inline void* sym_addr(const void* sym) {
    void* p = nullptr;
    cudaGetSymbolAddress(&p, sym);
    return p;
}

extern "C" void kernel_launch(void* const* d_in, const int* in_sizes, int n_in,
                              void* d_out, int out_size)
{
    const float* adj = (const float*)d_in[0];
    const float* x   = (const float*)d_in[1];
    const float* W1  = (const float*)d_in[2];
    const float* W2  = (const float*)d_in[3];
    const float* Wm1 = (const float*)d_in[4];
    const float* Wm2 = (const float*)d_in[5];
    const float* Wm3 = (const float*)d_in[6];
    const float* Wt  = (const float*)d_in[7];
    const float* bt  = (const float*)d_in[8];

    float* out = (float*)d_out;
    float* out_pred = out;
    float* out_x1   = out + (size_t)NN * NN;
    float* out_x2   = out_x1 + (size_t)NN * H1;
    float* out_z    = out_x2 + (size_t)NN * H2;

    float* t1 = (float*)sym_addr(g_t1);
    float* t2 = (float*)sym_addr(g_t2);
    float* tm = (float*)sym_addr(g_tm);
    __nv_bfloat16* xh  = (__nv_bfloat16*)sym_addr(g_xh);
    __nv_bfloat16* xl  = (__nv_bfloat16*)sym_addr(g_xl);
    __nv_bfloat16* x1h = (__nv_bfloat16*)sym_addr(g_x1h);
    __nv_bfloat16* x1l = (__nv_bfloat16*)sym_addr(g_x1l);
    __nv_bfloat16* x2h = (__nv_bfloat16*)sym_addr(g_x2h);
    __nv_bfloat16* x2l = (__nv_bfloat16*)sym_addr(g_x2l);
    __nv_bfloat16* zh  = (__nv_bfloat16*)sym_addr(g_zh);
    __nv_bfloat16* zl  = (__nv_bfloat16*)sym_addr(g_zl);
    __half* zf  = (__half*)sym_addr(g_zf);
    __half* tzf = (__half*)sym_addr(g_tzf);
    __nv_bfloat16* W1h = (__nv_bfloat16*)sym_addr(g_W1h);
    __nv_bfloat16* W1l = (__nv_bfloat16*)sym_addr(g_W1l);
    __nv_bfloat16* W2h = (__nv_bfloat16*)sym_addr(g_W2h);
    __nv_bfloat16* W2l = (__nv_bfloat16*)sym_addr(g_W2l);
    __nv_bfloat16* Wmh = (__nv_bfloat16*)sym_addr(g_Wmh);
    __nv_bfloat16* Wml = (__nv_bfloat16*)sym_addr(g_Wml);
    __nv_bfloat16* Wth = (__nv_bfloat16*)sym_addr(g_Wth);
    __nv_bfloat16* Wtl = (__nv_bfloat16*)sym_addr(g_Wtl);

    cudaFuncSetAttribute((const void*)gemm3<0>,
                         cudaFuncAttributeMaxDynamicSharedMemorySize, SMEM_BYTES);
    cudaFuncSetAttribute((const void*)gemm3<1>,
                         cudaFuncAttributeMaxDynamicSharedMemorySize, SMEM_BYTES);
    cudaFuncSetAttribute((const void*)pred_f16,
                         cudaFuncAttributeMaxDynamicSharedMemorySize, PF_SMEM);

    // 0. merged split of all static inputs (single launch)
    {
        SplitArgs a;
        const float* srcs[NSEG] = {x, W1, W2, Wm1, Wm2, Wm3, Wt};
        __nv_bfloat16* his[NSEG] = {xh, W1h, W2h, Wmh, Wmh + 64 * H2, Wmh + 128 * H2, Wth};
        __nv_bfloat16* los[NSEG] = {xl, W1l, W2l, Wml, Wml + 64 * H2, Wml + 128 * H2, Wtl};
        int ns[NSEG] = {NN * IN_DIM / 4, H1 * IN_DIM / 4, H2 * H1 / 4,
                        64 * H2 / 4, 64 * H2 / 4, 64 * H2 / 4, ZD * ZD / 4};
        int off = 0;
        for (int s = 0; s < NSEG; s++) {
            a.src[s] = (const float4*)srcs[s];
            a.hi[s]  = (uint32_t*)his[s];
            a.lo[s]  = (uint32_t*)los[s];
            a.nq[s]  = ns[s];
            a.blk_off[s] = off;
            off += (ns[s] + 255) / 256;
        }
        a.blk_off[NSEG] = off;
        split_all_kernel<<<off, 256>>>(a);
    }

    build_csr_kernel<<<NN / 8, 256>>>(adj);

    // t1 = x @ W1^T
    gemm3<0><<<dim3(H1 / GBN, NN / GBM), 128, SMEM_BYTES>>>(
        xh, xl, W1h, W1l, nullptr, t1, nullptr, NN, H1, IN_DIM, H1);
    // x1 = relu(adj@t1) -> planes; out_x1 = sigmoid   (ncq=128, 4 rows/CTA)
    spmm4_kernel<1><<<NN / 4, 512>>>(
        (const float4*)t1, H1 / 4, 4, (float4*)out_x1,
        (uint2*)x1h, (uint2*)x1l, nullptr);
    // t2 = x1 @ W2^T
    gemm3<0><<<dim3(H2 / GBN, NN / GBM), 128, SMEM_BYTES>>>(
        x1h, x1l, W2h, W2l, nullptr, t2, nullptr, NN, H2, H1, H2);
    // x2 planes + sigmoid   (ncq=64, 8 rows/CTA)
    spmm4_kernel<1><<<NN / 8, 512>>>(
        (const float4*)t2, H2 / 4, 8, (float4*)out_x2,
        (uint2*)x2h, (uint2*)x2l, nullptr);
    // tm = x2 @ Wm^T
    gemm3<0><<<dim3(2, NN / GBM), 128, SMEM_BYTES>>>(
        x2h, x2l, Wmh, Wml, nullptr, tm, nullptr, NN, ZD, H2, ZD);
    // z = adj @ tm -> fp32 out + bf16 planes + fp16 plane  (ncq=48, 16 rows/CTA)
    spmm4_kernel<0><<<NN / 16, 768>>>(
        (const float4*)tm, ZD / 4, 16, (float4*)out_z,
        (uint2*)zh, (uint2*)zl, (uint2*)zf);
    // tz = leaky(z @ Wt^T + bt) -> fp16 plane only
    gemm3<1><<<dim3(2, NN / GBM), 128, SMEM_BYTES>>>(
        zh, zl, Wth, Wtl, bt, nullptr, tzf, NN, ZD, ZD, ZD);
    // pred = zf @ tzf^T  (fp16 single pass)
    pred_f16<<<dim3(NN / 128, NN / 128), 128, PF_SMEM>>>(zf, tzf, out_pred);

    (void)in_sizes; (void)n_in; (void)out_size;
}